// round 3
// baseline (speedup 1.0000x reference)
#include <cuda_runtime.h>
#include <math_constants.h>

#define NBOX 4096
#define BATCH 16
#define MAXP 300
#define KEPT_PAD 304
#define NTHREADS 256

// Static shared (~39.3 KB): no dynamic smem, no cudaFuncSetAttribute.
//   key   : float[4096]  16 KB   sort keys (score or -inf)
//   sidx  : int  [4096]  16 KB   permutation (original indices)
//   kbox  : float4[304]  4.75 KB kept boxes
//   karea : float [304]  1.19 KB kept areas
//   kpos  : int   [304]  1.19 KB kept sorted-positions

__global__ __launch_bounds__(NTHREADS, 1)
void nms_kernel(const float* __restrict__ proposals,
                const float* __restrict__ cls_scores,
                float* __restrict__ out)
{
    __shared__ float  key[NBOX];
    __shared__ int    sidx[NBOX];
    __shared__ float4 kbox[KEPT_PAD];
    __shared__ float  karea[KEPT_PAD];
    __shared__ int    kpos[KEPT_PAD];
    __shared__ int    sV;
    __shared__ int    sNk;

    const int b   = blockIdx.x;
    const int tid = threadIdx.x;
    const float* cls  = cls_scores + (size_t)b * NBOX * 2;
    const float* prop = proposals  + (size_t)b * NBOX * 4;

    if (tid == 0) sV = 0;
    __syncthreads();

    // ---- build sort keys: valid -> score, invalid -> -inf ----
    int vloc = 0;
    for (int i = tid; i < NBOX; i += NTHREADS) {
        float s = __ldg(&cls[i * 2 + 1]);
        bool valid = s > 0.5f;                 // exact strict compare per reference
        key[i]  = valid ? s : -CUDART_INF_F;
        sidx[i] = i;
        vloc += valid ? 1 : 0;
    }
    atomicAdd(&sV, vloc);
    __syncthreads();

    // ---- bitonic sort on (key desc, idx asc): matches stable argsort(-score) ----
    for (int k = 2; k <= NBOX; k <<= 1) {
        for (int j = k >> 1; j > 0; j >>= 1) {
            for (int i = tid; i < NBOX; i += NTHREADS) {
                int ixj = i ^ j;
                if (ixj > i) {
                    float ka = key[i],  kb = key[ixj];
                    int   ia = sidx[i], ib = sidx[ixj];
                    // true if element at ixj belongs BEFORE element at i
                    bool beforeBA = (kb > ka) || (kb == ka && ib < ia);
                    bool dir = ((i & k) == 0);
                    if (beforeBA == dir) {
                        key[i] = kb;  key[ixj] = ka;
                        sidx[i] = ib; sidx[ixj] = ia;
                    }
                }
            }
            __syncthreads();
        }
    }

    // ---- greedy NMS: single-warp kept-list scan, early exit at 300 kept ----
    // Candidate boxes read from global (L1-resident, broadcast across the warp).
    const int V = sV;
    if (tid < 32) {
        int cnt = 0;
        for (int i = 0; i < V && cnt < MAXP; ++i) {
            const float4 c = *(const float4*)(prop + (size_t)sidx[i] * 4);
            const float ca = __fmul_rn(c.z - c.x, c.w - c.y);
            bool sup = false;
            for (int t = tid; t < cnt; t += 32) {
                float4 kb = kbox[t];
                float ix1 = fmaxf(c.x, kb.x);
                float iy1 = fmaxf(c.y, kb.y);
                float ix2 = fminf(c.z, kb.z);
                float iy2 = fminf(c.w, kb.w);
                float w = fmaxf(ix2 - ix1, 0.0f);
                float h = fmaxf(iy2 - iy1, 0.0f);
                float inter = __fmul_rn(w, h);           // single rounded mul
                float denom = (ca + karea[t]) - inter;   // add then sub, no FMA
                if (__fdiv_rn(inter, denom) >= 0.7f) sup = true;
            }
            unsigned m = __ballot_sync(0xffffffffu, sup);
            if (m == 0u) {
                if (tid == 0) {
                    kbox[cnt]  = c;
                    karea[cnt] = ca;
                    kpos[cnt]  = i;
                }
                cnt++;
                __syncwarp(0xffffffffu);
            }
        }
        if (tid == 0) sNk = cnt;
    }
    __syncthreads();

    // ---- epilogue: sel[k] = order[pos[min(k, nk-1)]]; nk==0 -> order[n-1] ----
    const int nk = sNk;
    float* outBoxes  = out;                                   // [16,300,4]
    float* outScores = out + (size_t)BATCH * MAXP * 4;        // [16,300]
    for (int k = tid; k < MAXP; k += NTHREADS) {
        int p = (nk == 0) ? (NBOX - 1) : kpos[k < nk ? k : nk - 1];
        int sel = sidx[p];
        float4 bb = *(const float4*)(prop + (size_t)sel * 4);
        *(float4*)(outBoxes + ((size_t)b * MAXP + k) * 4) = bb;
        outScores[(size_t)b * MAXP + k] = __ldg(&cls[sel * 2 + 1]);
    }
}

extern "C" void kernel_launch(void* const* d_in, const int* in_sizes, int n_in,
                              void* d_out, int out_size)
{
    const float* proposals = (const float*)d_in[0];   // [16,4096,4] f32
    const float* cls       = (const float*)d_in[1];   // [16,4096,2] f32
    float* out             = (float*)d_out;           // 16*300*4 boxes, then 16*300 scores

    nms_kernel<<<BATCH, NTHREADS>>>(proposals, cls, out);
}

// round 4
// speedup vs baseline: 5.4112x; 5.4112x over previous
#include <cuda_runtime.h>
#include <math_constants.h>

#define NBOX 4096
#define BATCH 16
#define MAXP 300
#define KEPT_PAD 304
#define NTHREADS 1024
#define CHUNK 64

// Static shared (~41 KB, under the 48 KB static limit; no cudaFuncSetAttribute):
//   skey    : u64 [4096]   32 KB   packed (score_bits, NBOX-1-i) sort keys
//   kbox    : f4  [304]    4.75 KB kept boxes
//   karea   : f32 [304]
//   kidx    : int [304]    kept original indices
//   cb/car/cidx : chunk candidates (64)
//   chMaskLo/Hi : 64x u32  within-chunk suppression bitmasks
//   supMask     : 2x u32   chunk-vs-kept suppression bits

__device__ __forceinline__ bool iou_ge(float4 a, float aa, float4 b, float ba)
{
    float ix1 = fmaxf(a.x, b.x);
    float iy1 = fmaxf(a.y, b.y);
    float ix2 = fminf(a.z, b.z);
    float iy2 = fminf(a.w, b.w);
    float w = fmaxf(ix2 - ix1, 0.0f);
    float h = fmaxf(iy2 - iy1, 0.0f);
    float inter = __fmul_rn(w, h);          // single rounded mul
    float denom = (aa + ba) - inter;        // add then sub, no FMA contraction
    return __fdiv_rn(inter, denom) >= 0.7f;
}

__global__ __launch_bounds__(NTHREADS, 1)
void nms_kernel(const float* __restrict__ proposals,
                const float* __restrict__ cls_scores,
                float* __restrict__ out)
{
    __shared__ unsigned long long skey[NBOX];
    __shared__ float4 kbox[KEPT_PAD];
    __shared__ float  karea[KEPT_PAD];
    __shared__ int    kidx[KEPT_PAD];
    __shared__ float4 cb[CHUNK];
    __shared__ float  car[CHUNK];
    __shared__ int    cidx[CHUNK];
    __shared__ unsigned int chMaskLo[CHUNK];
    __shared__ unsigned int chMaskHi[CHUNK];
    __shared__ unsigned int supMask[2];
    __shared__ int sV;
    __shared__ int sCnt;

    const int b   = blockIdx.x;
    const int tid = threadIdx.x;
    const float* cls  = cls_scores + (size_t)b * NBOX * 2;
    const float* prop = proposals  + (size_t)b * NBOX * 4;

    if (tid == 0) { sV = 0; sCnt = 0; }
    __syncthreads();

    // ---- build packed keys: (score_bits << 32) | (NBOX-1-i); invalid -> score_bits=0 ----
    // score > 0.5 => positive float => bits monotone with value; descending u64 sort
    // reproduces stable argsort(-score) exactly (ties broken by smaller i first).
    int vloc = 0;
    for (int i = tid; i < NBOX; i += NTHREADS) {
        float s = __ldg(&cls[i * 2 + 1]);
        bool valid = s > 0.5f;                       // exact strict compare per reference
        unsigned int sb = valid ? __float_as_uint(s) : 0u;
        skey[i] = ((unsigned long long)sb << 32) | (unsigned int)(NBOX - 1 - i);
        vloc += valid ? 1 : 0;
    }
    atomicAdd(&sV, vloc);
    __syncthreads();

    // ---- bitonic sort, descending on packed u64 ----
    for (int k = 2; k <= NBOX; k <<= 1) {
        for (int j = k >> 1; j > 0; j >>= 1) {
            #pragma unroll
            for (int i = tid; i < NBOX; i += NTHREADS) {
                int ixj = i ^ j;
                if (ixj > i) {
                    unsigned long long ka = skey[i], kb = skey[ixj];
                    bool beforeBA = (kb > ka);            // descending; keys unique
                    bool dir = ((i & k) == 0);
                    if (beforeBA == dir) { skey[i] = kb; skey[ixj] = ka; }
                }
            }
            __syncthreads();
        }
    }

    // ---- chunk-parallel greedy NMS ----
    const int V = sV;
    for (int base = 0; base < V && sCnt < MAXP; base += CHUNK) {
        const int chunkN = (V - base < CHUNK) ? (V - base) : CHUNK;

        // stage chunk candidates; clear masks
        if (tid < CHUNK) {
            chMaskLo[tid] = 0u;
            chMaskHi[tid] = 0u;
            if (tid < 2) supMask[tid] = 0u;
            if (tid < chunkN) {
                int oi = NBOX - 1 - (int)(unsigned int)(skey[base + tid] & 0xFFFFFFFFull);
                float4 bb = *(const float4*)(prop + (size_t)oi * 4);
                cb[tid]   = bb;
                car[tid]  = __fmul_rn(bb.z - bb.x, bb.w - bb.y);
                cidx[tid] = oi;
            }
        }
        __syncthreads();

        const int cnt = sCnt;

        // chunk vs already-kept: flag candidates overlapping any kept box
        for (int p = tid; p < chunkN * cnt; p += NTHREADS) {
            int c = p % CHUNK == p % CHUNK ? (p & (CHUNK - 1)) : 0;  // p & 63
            int t = p >> 6;
            if (iou_ge(cb[c], car[c], kbox[t], karea[t]))
                atomicOr(&supMask[c >> 5], 1u << (c & 31));
        }

        // within-chunk pairwise IoU bitmasks (i suppresses j>i if kept)
        for (int p = tid; p < CHUNK * CHUNK; p += NTHREADS) {
            int i = p >> 6, j = p & (CHUNK - 1);
            if (j > i && j < chunkN && i < chunkN) {
                if (iou_ge(cb[i], car[i], cb[j], car[j])) {
                    if (j < 32) atomicOr(&chMaskLo[i], 1u << j);
                    else        atomicOr(&chMaskHi[i], 1u << (j - 32));
                }
            }
        }
        __syncthreads();

        // serial resolve (thread 0): 64-step bitmask walk
        if (tid == 0) {
            unsigned long long sup =
                ((unsigned long long)supMask[1] << 32) | supMask[0];
            int c2 = cnt;
            for (int c = 0; c < chunkN && c2 < MAXP; ++c) {
                if (!((sup >> c) & 1ull)) {
                    kbox[c2]  = cb[c];
                    karea[c2] = car[c];
                    kidx[c2]  = cidx[c];
                    c2++;
                    sup |= ((unsigned long long)chMaskHi[c] << 32) | chMaskLo[c];
                }
            }
            sCnt = c2;
        }
        __syncthreads();
    }

    // ---- epilogue ----
    const int nk = sCnt;
    float* outBoxes  = out;                              // [16,300,4]
    float* outScores = out + (size_t)BATCH * MAXP * 4;   // [16,300]
    for (int k = tid; k < MAXP; k += NTHREADS) {
        float4 bb; int sel;
        if (nk == 0) {
            // reference: pos[0]=n -> clip n-1 -> order[n-1] (V==0 => identity order)
            sel = NBOX - 1 - (int)(unsigned int)(skey[NBOX - 1] & 0xFFFFFFFFull);
            bb = *(const float4*)(prop + (size_t)sel * 4);
        } else {
            int kk = k < nk ? k : nk - 1;
            bb = kbox[kk];
            sel = kidx[kk];
        }
        *(float4*)(outBoxes + ((size_t)b * MAXP + k) * 4) = bb;
        outScores[(size_t)b * MAXP + k] = __ldg(&cls[sel * 2 + 1]);
    }
}

extern "C" void kernel_launch(void* const* d_in, const int* in_sizes, int n_in,
                              void* d_out, int out_size)
{
    const float* proposals = (const float*)d_in[0];   // [16,4096,4] f32
    const float* cls       = (const float*)d_in[1];   // [16,4096,2] f32
    float* out             = (float*)d_out;           // boxes then scores

    nms_kernel<<<BATCH, NTHREADS>>>(proposals, cls, out);
}

// round 8
// speedup vs baseline: 6.8027x; 1.2571x over previous
#include <cuda_runtime.h>

#define NBOX 4096
#define BATCH 16
#define MAXP 300
#define KEPT_PAD 304
#define NTHREADS 1024
#define CHUNK 64
#define TARGET 768

// IoU decision with the exact single-rounded op sequence of the reference
// (max/min, sub, one mul, add-then-sub, one div; no FMA contraction).
__device__ __forceinline__ bool iou_ge(float4 a, float aa, float4 b, float ba)
{
    float ix1 = fmaxf(a.x, b.x);
    float iy1 = fmaxf(a.y, b.y);
    float ix2 = fminf(a.z, b.z);
    float iy2 = fminf(a.w, b.w);
    float w = fmaxf(ix2 - ix1, 0.0f);
    float h = fmaxf(iy2 - iy1, 0.0f);
    float inter = __fmul_rn(w, h);
    float denom = (aa + ba) - inter;
    return __fdiv_rn(inter, denom) >= 0.7f;
}

__global__ __launch_bounds__(NTHREADS, 1)
void nms_kernel(const float* __restrict__ proposals,
                const float* __restrict__ cls_scores,
                float* __restrict__ out)
{
    __shared__ unsigned long long skey[NBOX];       // band buffer (worst case: all)
    __shared__ unsigned int hist[256];
    __shared__ unsigned int suf[257];
    __shared__ float4 kbox[KEPT_PAD];
    __shared__ float  karea[KEPT_PAD];
    __shared__ int    kidx[KEPT_PAD];
    __shared__ float4 cb[CHUNK];
    __shared__ float  car[CHUNK];
    __shared__ int    cidx[CHUNK];
    __shared__ unsigned int chMaskLo[CHUNK];
    __shared__ unsigned int chMaskHi[CHUNK];
    __shared__ unsigned int supMask[2];
    __shared__ unsigned int sMin, sMax, sSelCtr;
    __shared__ int sV, sCnt, sBinHi, sBinLo, sSelN;

    const int b   = blockIdx.x;
    const int tid = threadIdx.x;
    const float* cls  = cls_scores + (size_t)b * NBOX * 2;
    const float* prop = proposals  + (size_t)b * NBOX * 4;

    if (tid == 0) { sV = 0; sCnt = 0; sBinHi = 255; sMin = 0xFFFFFFFFu; sMax = 0u; }
    if (tid < 256) hist[tid] = 0u;
    __syncthreads();

    // ---- phase 0: validity, count, min/max of valid score bits ----
    // score > 0.5 => positive float => integer bit pattern monotone with value.
    int vloc = 0;
    unsigned mn = 0xFFFFFFFFu, mx = 0u;
    for (int i = tid; i < NBOX; i += NTHREADS) {
        float s = __ldg(&cls[i * 2 + 1]);
        if (s > 0.5f) {                               // exact strict compare
            unsigned sb = __float_as_uint(s);
            vloc++;
            mn = sb < mn ? sb : mn;
            mx = sb > mx ? sb : mx;
        }
    }
    atomicAdd(&sV, vloc);
    if (vloc) { atomicMin(&sMin, mn); atomicMax(&sMax, mx); }
    __syncthreads();

    const int V = sV;
    const unsigned minSb = sMin;
    const unsigned long long rangeP1 = (unsigned long long)(sMax - sMin) + 1ull;

    // ---- phase 1: 256-bin monotone histogram over valid score bits ----
    if (V > 0) {
        for (int i = tid; i < NBOX; i += NTHREADS) {
            float s = __ldg(&cls[i * 2 + 1]);
            if (s > 0.5f) {
                unsigned sb = __float_as_uint(s);
                unsigned bin = (unsigned)((((unsigned long long)(sb - minSb)) << 8) / rangeP1);
                atomicAdd(&hist[bin], 1u);
            }
        }
    }
    __syncthreads();
    if (tid < 256) {                                   // suffix counts suf[t] = sum hist[t..255]
        unsigned sum = 0;
        for (int bb = tid; bb < 256; bb++) sum += hist[bb];
        suf[tid] = sum;
    }
    if (tid == 0) suf[256] = 0u;

    // ---- band loop: highest score bins first; exact global descending order.
    // Bounded iteration count (each pass lowers sBinHi by >=1, or sCnt reaches
    // MAXP); the 260 cap is unreachable and exists purely as a hang guard.
    for (int iter = 0; iter < 260; ++iter) {
        __syncthreads();
        int cnt = sCnt, binHi = sBinHi;
        if (V == 0 || cnt >= MAXP || binHi < 0) break;

        if (tid == 0) {
            unsigned tail = suf[binHi + 1];
            int lo = 0;
            if (suf[0] - tail >= TARGET) {             // largest lo with band count >= TARGET
                int L = 0, R = binHi;
                while (L < R) {
                    int m = (L + R + 1) >> 1;
                    if (suf[m] - tail >= TARGET) L = m; else R = m - 1;
                }
                lo = L;
            }
            sBinLo = lo;
            sSelN  = (int)(suf[lo] - tail);
            sSelCtr = 0u;
        }
        __syncthreads();
        const int binLo = sBinLo, selN = sSelN;

        if (selN > 0) {
            // select band members (order irrelevant; keys unique, sort fixes order)
            for (int i = tid; i < NBOX; i += NTHREADS) {
                float s = __ldg(&cls[i * 2 + 1]);
                if (s > 0.5f) {
                    unsigned sb = __float_as_uint(s);
                    int bin = (int)((((unsigned long long)(sb - minSb)) << 8) / rangeP1);
                    if (bin >= binLo && bin <= binHi) {
                        unsigned p = atomicAdd(&sSelCtr, 1u);
                        skey[p] = ((unsigned long long)sb << 32) | (unsigned)(NBOX - 1 - i);
                    }
                }
            }
            __syncthreads();
            int S = 1; while (S < selN) S <<= 1;       // pad to pow2 with 0-keys (sink)
            for (int i = tid; i < S; i += NTHREADS)
                if (i >= selN) skey[i] = 0ull;
            __syncthreads();

            // bitonic sort, descending (keys unique among valid)
            for (int k = 2; k <= S; k <<= 1) {
                for (int j = k >> 1; j > 0; j >>= 1) {
                    for (int i = tid; i < S; i += NTHREADS) {
                        int ixj = i ^ j;
                        if (ixj > i) {
                            unsigned long long ka = skey[i], kb = skey[ixj];
                            bool beforeBA = (kb > ka);
                            bool dir = ((i & k) == 0);
                            if (beforeBA == dir) { skey[i] = kb; skey[ixj] = ka; }
                        }
                    }
                    __syncthreads();
                }
            }

            // chunk-parallel greedy NMS over this band
            for (int base = 0; base < selN; base += CHUNK) {
                int c0 = sCnt;                          // barrier-protected uniform read
                if (c0 >= MAXP) break;
                const int chunkN = (selN - base < CHUNK) ? (selN - base) : CHUNK;

                if (tid < CHUNK) {
                    chMaskLo[tid] = 0u;
                    chMaskHi[tid] = 0u;
                    if (tid < 2) supMask[tid] = 0u;
                    if (tid < chunkN) {
                        int oi = NBOX - 1 - (int)(unsigned)(skey[base + tid] & 0xFFFFFFFFull);
                        float4 bb = *(const float4*)(prop + (size_t)oi * 4);
                        cb[tid]   = bb;
                        car[tid]  = __fmul_rn(bb.z - bb.x, bb.w - bb.y);
                        cidx[tid] = oi;
                    }
                }
                __syncthreads();

                // chunk vs already-kept
                for (int p = tid; p < CHUNK * c0; p += NTHREADS) {
                    int c = p & (CHUNK - 1);
                    int t = p >> 6;
                    if (c < chunkN && iou_ge(cb[c], car[c], kbox[t], karea[t]))
                        atomicOr(&supMask[c >> 5], 1u << (c & 31));
                }
                // within-chunk pairwise (i suppresses j>i if i kept)
                for (int p = tid; p < CHUNK * CHUNK; p += NTHREADS) {
                    int i = p >> 6, j = p & (CHUNK - 1);
                    if (j > i && j < chunkN) {
                        if (iou_ge(cb[i], car[i], cb[j], car[j])) {
                            if (j < 32) atomicOr(&chMaskLo[i], 1u << j);
                            else        atomicOr(&chMaskHi[i], 1u << (j - 32));
                        }
                    }
                }
                __syncthreads();

                if (tid == 0) {                         // serial bitmask resolve
                    unsigned long long sup =
                        ((unsigned long long)supMask[1] << 32) | supMask[0];
                    int c2 = c0;
                    for (int c = 0; c < chunkN && c2 < MAXP; ++c) {
                        if (!((sup >> c) & 1ull)) {
                            kbox[c2]  = cb[c];
                            karea[c2] = car[c];
                            kidx[c2]  = cidx[c];
                            c2++;
                            sup |= ((unsigned long long)chMaskHi[c] << 32) | chMaskLo[c];
                        }
                    }
                    sCnt = c2;
                }
                __syncthreads();
            }
        }
        if (tid == 0) sBinHi = binLo - 1;
    }

    __syncthreads();
    // ---- epilogue: pad with last kept; nk==0 (<=> V==0) -> order[n-1] = 4095 ----
    const int nk = sCnt;
    float* outBoxes  = out;                              // [16,300,4]
    float* outScores = out + (size_t)BATCH * MAXP * 4;   // [16,300]
    for (int k = tid; k < MAXP; k += NTHREADS) {
        float4 bb; int sel;
        if (nk == 0) {
            sel = NBOX - 1;
            bb = *(const float4*)(prop + (size_t)sel * 4);
        } else {
            int kk = k < nk ? k : nk - 1;
            bb = kbox[kk];
            sel = kidx[kk];
        }
        *(float4*)(outBoxes + ((size_t)b * MAXP + k) * 4) = bb;
        outScores[(size_t)b * MAXP + k] = __ldg(&cls[sel * 2 + 1]);
    }
}

extern "C" void kernel_launch(void* const* d_in, const int* in_sizes, int n_in,
                              void* d_out, int out_size)
{
    const float* proposals = (const float*)d_in[0];   // [16,4096,4] f32
    const float* cls       = (const float*)d_in[1];   // [16,4096,2] f32
    float* out             = (float*)d_out;           // boxes then scores

    nms_kernel<<<BATCH, NTHREADS>>>(proposals, cls, out);
}

// round 9
// speedup vs baseline: 8.8532x; 1.3014x over previous
#include <cuda_runtime.h>

#define NBOX 4096
#define BATCH 16
#define MAXP 300
#define KEPT_PAD 304
#define NTHREADS 1024
#define CHUNK 64
#define TARGET 768

// IoU decision with the exact single-rounded op sequence of the reference
// (max/min, sub, one mul, add-then-sub, one div; no FMA contraction).
__device__ __forceinline__ bool iou_ge(float4 a, float aa, float4 b, float ba)
{
    float ix1 = fmaxf(a.x, b.x);
    float iy1 = fmaxf(a.y, b.y);
    float ix2 = fminf(a.z, b.z);
    float iy2 = fminf(a.w, b.w);
    float w = fmaxf(ix2 - ix1, 0.0f);
    float h = fmaxf(iy2 - iy1, 0.0f);
    float inter = __fmul_rn(w, h);
    float denom = (aa + ba) - inter;
    return __fdiv_rn(inter, denom) >= 0.7f;
}

// Fixed monotone binning for scores > 0.5: bits - bits(0.5f), top byte-ish.
// Monotone non-decreasing in score bits; clamp keeps it monotone for s >= 1.
__device__ __forceinline__ unsigned score_bin(unsigned sb)
{
    unsigned d = (sb - 0x3F000000u) >> 15;
    return d > 255u ? 255u : d;
}

__global__ __launch_bounds__(NTHREADS, 1)
void nms_kernel(const float* __restrict__ proposals,
                const float* __restrict__ cls_scores,
                float* __restrict__ out)
{
    __shared__ unsigned long long skey[NBOX];       // band buffer (worst case: all)
    __shared__ unsigned int hist[256];
    __shared__ unsigned int suf[257];
    __shared__ float4 kbox[KEPT_PAD];
    __shared__ float  karea[KEPT_PAD];
    __shared__ int    kidx[KEPT_PAD];
    __shared__ float4 cb[CHUNK];
    __shared__ float  car[CHUNK];
    __shared__ int    cidx[CHUNK];
    __shared__ unsigned int chMaskLo[CHUNK];
    __shared__ unsigned int chMaskHi[CHUNK];
    __shared__ unsigned int supMask[2];
    __shared__ unsigned int sSelCtr;
    __shared__ int sV, sCnt, sBinHi, sBinLo, sSelN;

    const int b   = blockIdx.x;
    const int tid = threadIdx.x;
    const float* cls  = cls_scores + (size_t)b * NBOX * 2;
    const float* prop = proposals  + (size_t)b * NBOX * 4;

    if (tid == 0) { sV = 0; sCnt = 0; sBinHi = 255; }
    if (tid < 256) hist[tid] = 0u;
    __syncthreads();

    // ---- phase 0 (fused): validity + histogram with fixed monotone bins ----
    int vloc = 0;
    for (int i = tid; i < NBOX; i += NTHREADS) {
        float s = __ldg(&cls[i * 2 + 1]);
        if (s > 0.5f) {                               // exact strict compare
            atomicAdd(&hist[score_bin(__float_as_uint(s))], 1u);
            vloc++;
        }
    }
    atomicAdd(&sV, vloc);
    __syncthreads();

    if (tid < 256) {                                   // suffix counts suf[t] = sum hist[t..255]
        unsigned sum = 0;
        for (int bb = tid; bb < 256; bb++) sum += hist[bb];
        suf[tid] = sum;
    }
    if (tid == 0) suf[256] = 0u;
    const int V = sV;

    // ---- band loop: highest bins first; exact global descending order.
    // Each pass lowers sBinHi or reaches MAXP; 260 cap is an unreachable hang guard.
    for (int iter = 0; iter < 260; ++iter) {
        __syncthreads();
        int cnt = sCnt, binHi = sBinHi;
        if (V == 0 || cnt >= MAXP || binHi < 0) break;

        if (tid == 0) {
            unsigned tail = suf[binHi + 1];
            int lo = 0;
            if (suf[0] - tail >= TARGET) {             // largest lo with band count >= TARGET
                int L = 0, R = binHi;
                while (L < R) {
                    int m = (L + R + 1) >> 1;
                    if (suf[m] - tail >= TARGET) L = m; else R = m - 1;
                }
                lo = L;
            }
            sBinLo = lo;
            sSelN  = (int)(suf[lo] - tail);
            sSelCtr = 0u;
        }
        __syncthreads();
        const int binLo = sBinLo, selN = sSelN;

        if (selN > 0) {
            // select band members (order irrelevant; unique keys, sort fixes order)
            for (int i = tid; i < NBOX; i += NTHREADS) {
                float s = __ldg(&cls[i * 2 + 1]);
                if (s > 0.5f) {
                    unsigned sb = __float_as_uint(s);
                    int bin = (int)score_bin(sb);
                    if (bin >= binLo && bin <= binHi) {
                        unsigned p = atomicAdd(&sSelCtr, 1u);
                        skey[p] = ((unsigned long long)sb << 32) | (unsigned)(NBOX - 1 - i);
                    }
                }
            }
            __syncthreads();

            if (selN <= 1024) {
                // ---- hybrid register/shfl bitonic, S = 1024 fixed, descending ----
                const int S = 1024;
                for (int i = tid; i < S; i += NTHREADS)
                    if (i >= selN) skey[i] = 0ull;     // zero sinks sort to the end
                __syncthreads();

                unsigned long long x = skey[tid];
                #pragma unroll
                for (int k = 2; k <= 32; k <<= 1) {
                    #pragma unroll
                    for (int j = k >> 1; j > 0; j >>= 1) {
                        unsigned long long y = __shfl_xor_sync(0xffffffffu, x, j);
                        bool up      = ((tid & k) != 0);
                        bool lower   = ((tid & j) == 0);
                        bool wantMin = (lower == up);
                        bool takeY   = wantMin ? (y < x) : (y > x);
                        if (takeY) x = y;
                    }
                }
                skey[tid] = x;
                __syncthreads();

                for (int k = 64; k <= S; k <<= 1) {
                    for (int j = k >> 1; j >= 32; j >>= 1) {
                        int i = tid, ixj = i ^ j;
                        if (ixj > i) {
                            unsigned long long ka = skey[i], kb = skey[ixj];
                            bool beforeBA = (kb > ka);
                            bool dir = ((i & k) == 0);
                            if (beforeBA == dir) { skey[i] = kb; skey[ixj] = ka; }
                        }
                        __syncthreads();
                    }
                    x = skey[tid];
                    #pragma unroll
                    for (int j = 16; j > 0; j >>= 1) {
                        unsigned long long y = __shfl_xor_sync(0xffffffffu, x, j);
                        bool up      = ((tid & k) != 0);
                        bool lower   = ((tid & j) == 0);
                        bool wantMin = (lower == up);
                        bool takeY   = wantMin ? (y < x) : (y > x);
                        if (takeY) x = y;
                    }
                    skey[tid] = x;
                    __syncthreads();
                }
            } else {
                // ---- fallback: full smem bitonic for oversized bands ----
                int S = 1; while (S < selN) S <<= 1;
                for (int i = tid; i < S; i += NTHREADS)
                    if (i >= selN) skey[i] = 0ull;
                __syncthreads();
                for (int k = 2; k <= S; k <<= 1) {
                    for (int j = k >> 1; j > 0; j >>= 1) {
                        for (int i = tid; i < S; i += NTHREADS) {
                            int ixj = i ^ j;
                            if (ixj > i) {
                                unsigned long long ka = skey[i], kb = skey[ixj];
                                bool beforeBA = (kb > ka);
                                bool dir = ((i & k) == 0);
                                if (beforeBA == dir) { skey[i] = kb; skey[ixj] = ka; }
                            }
                        }
                        __syncthreads();
                    }
                }
            }

            // ---- chunk-parallel greedy NMS over this band ----
            for (int base = 0; base < selN; base += CHUNK) {
                int c0 = sCnt;                          // barrier-protected uniform read
                if (c0 >= MAXP) break;
                const int chunkN = (selN - base < CHUNK) ? (selN - base) : CHUNK;

                if (tid < CHUNK) {
                    chMaskLo[tid] = 0u;
                    chMaskHi[tid] = 0u;
                    if (tid < 2) supMask[tid] = 0u;
                    if (tid < chunkN) {
                        int oi = NBOX - 1 - (int)(unsigned)(skey[base + tid] & 0xFFFFFFFFull);
                        float4 bb = *(const float4*)(prop + (size_t)oi * 4);
                        cb[tid]   = bb;
                        car[tid]  = __fmul_rn(bb.z - bb.x, bb.w - bb.y);
                        cidx[tid] = oi;
                    }
                }
                __syncthreads();

                // chunk vs already-kept
                for (int p = tid; p < CHUNK * c0; p += NTHREADS) {
                    int c = p & (CHUNK - 1);
                    int t = p >> 6;
                    if (c < chunkN && iou_ge(cb[c], car[c], kbox[t], karea[t]))
                        atomicOr(&supMask[c >> 5], 1u << (c & 31));
                }
                // within-chunk pairwise (i suppresses j>i if i kept)
                for (int p = tid; p < CHUNK * CHUNK; p += NTHREADS) {
                    int i = p >> 6, j = p & (CHUNK - 1);
                    if (j > i && j < chunkN) {
                        if (iou_ge(cb[i], car[i], cb[j], car[j])) {
                            if (j < 32) atomicOr(&chMaskLo[i], 1u << j);
                            else        atomicOr(&chMaskHi[i], 1u << (j - 32));
                        }
                    }
                }
                __syncthreads();

                // ---- warp-uniform shfl resolve (warp 0) + parallel append ----
                if (tid < 32) {
                    unsigned long long m64a =
                        ((unsigned long long)chMaskHi[tid] << 32) | chMaskLo[tid];
                    unsigned long long m64b =
                        ((unsigned long long)chMaskHi[tid + 32] << 32) | chMaskLo[tid + 32];
                    unsigned long long sup =
                        ((unsigned long long)supMask[1] << 32) | supMask[0];
                    unsigned long long kept = 0ull;
                    int c2 = c0;
                    for (int c = 0; c < chunkN; ++c) {
                        if (!((sup >> c) & 1ull)) {
                            kept |= 1ull << c;
                            c2++;
                            unsigned long long m = (c < 32)
                                ? __shfl_sync(0xffffffffu, m64a, c)
                                : __shfl_sync(0xffffffffu, m64b, c - 32);
                            sup |= m;
                            if (c2 >= MAXP) break;      // 300th kept, stop
                        }
                    }
                    #pragma unroll
                    for (int h = 0; h < 2; ++h) {
                        int c = tid + h * 32;
                        if (c < chunkN && ((kept >> c) & 1ull)) {
                            int slot = c0 + __popcll(kept & ((1ull << c) - 1ull));
                            kbox[slot]  = cb[c];
                            karea[slot] = car[c];
                            kidx[slot]  = cidx[c];
                        }
                    }
                    if (tid == 0) sCnt = c2;
                }
                __syncthreads();
            }
        }
        if (tid == 0) sBinHi = binLo - 1;
    }

    __syncthreads();
    // ---- epilogue: pad with last kept; nk==0 (<=> V==0) -> order[n-1] = 4095 ----
    const int nk = sCnt;
    float* outBoxes  = out;                              // [16,300,4]
    float* outScores = out + (size_t)BATCH * MAXP * 4;   // [16,300]
    for (int k = tid; k < MAXP; k += NTHREADS) {
        float4 bb; int sel;
        if (nk == 0) {
            sel = NBOX - 1;
            bb = *(const float4*)(prop + (size_t)sel * 4);
        } else {
            int kk = k < nk ? k : nk - 1;
            bb = kbox[kk];
            sel = kidx[kk];
        }
        *(float4*)(outBoxes + ((size_t)b * MAXP + k) * 4) = bb;
        outScores[(size_t)b * MAXP + k] = __ldg(&cls[sel * 2 + 1]);
    }
}

extern "C" void kernel_launch(void* const* d_in, const int* in_sizes, int n_in,
                              void* d_out, int out_size)
{
    const float* proposals = (const float*)d_in[0];   // [16,4096,4] f32
    const float* cls       = (const float*)d_in[1];   // [16,4096,2] f32
    float* out             = (float*)d_out;           // boxes then scores

    nms_kernel<<<BATCH, NTHREADS>>>(proposals, cls, out);
}

// round 10
// speedup vs baseline: 9.4782x; 1.0706x over previous
#include <cuda_runtime.h>

#define NBOX 4096
#define BATCH 16
#define MAXP 300
#define KEPT_PAD 304
#define NTHREADS 1024
#define CHUNK 64
#define TARGET 448

// IoU decision with the exact single-rounded op sequence of the reference.
__device__ __forceinline__ bool iou_ge(float4 a, float aa, float4 b, float ba)
{
    float ix1 = fmaxf(a.x, b.x);
    float iy1 = fmaxf(a.y, b.y);
    float ix2 = fminf(a.z, b.z);
    float iy2 = fminf(a.w, b.w);
    float w = fmaxf(ix2 - ix1, 0.0f);
    float h = fmaxf(iy2 - iy1, 0.0f);
    float inter = __fmul_rn(w, h);
    float denom = (aa + ba) - inter;
    return __fdiv_rn(inter, denom) >= 0.7f;
}

// Fixed monotone binning for scores > 0.5 (clamped; monotone non-decreasing).
__device__ __forceinline__ unsigned score_bin(unsigned sb)
{
    unsigned d = (sb - 0x3F000000u) >> 15;
    return d > 255u ? 255u : d;
}

__global__ __launch_bounds__(NTHREADS, 1)
void nms_kernel(const float* __restrict__ proposals,
                const float* __restrict__ cls_scores,
                float* __restrict__ out)
{
    __shared__ unsigned long long skey[NBOX];   // [0..V) vlist, then sorted band [0..S)
    __shared__ unsigned int hist[256];
    __shared__ unsigned int suf[257];
    __shared__ float4 kbox[KEPT_PAD];
    __shared__ float  karea[KEPT_PAD];
    __shared__ int    kidx[KEPT_PAD];
    __shared__ float4 cb[CHUNK];                // fallback staging only
    __shared__ float  car[CHUNK];
    __shared__ unsigned int chMaskLo[CHUNK];
    __shared__ unsigned int chMaskHi[CHUNK];
    __shared__ unsigned int supMask[2];
    __shared__ unsigned int sVCtr, sSelCtr;
    __shared__ int sCnt, sBinHi, sBinLo, sSelN;

    // Band box cache carved out of skey's tail (only used when selN <= 1024;
    // sorted keys then occupy skey[0..1023], no overlap).
    float4* bbuf = (float4*)(skey + 1024);      // 1024 * 16B = skey[1024..3071]
    float*  abuf = (float*)(skey + 3072);       // 1024 * 4B  = skey[3072..3583]

    const int b   = blockIdx.x;
    const int tid = threadIdx.x;
    const float* cls  = cls_scores + (size_t)b * NBOX * 2;
    const float* prop = proposals  + (size_t)b * NBOX * 4;

    if (tid == 0) { sVCtr = 0u; sCnt = 0; sBinHi = 255; }
    if (tid < 256) hist[tid] = 0u;
    __syncthreads();

    // ---- phase 0 (fused): validity + histogram + compacted vlist in smem ----
    for (int i = tid; i < NBOX; i += NTHREADS) {
        float s = __ldg(&cls[i * 2 + 1]);
        if (s > 0.5f) {                          // exact strict compare
            unsigned sb = __float_as_uint(s);
            atomicAdd(&hist[score_bin(sb)], 1u);
            unsigned p = atomicAdd(&sVCtr, 1u);
            skey[p] = ((unsigned long long)sb << 32) | (unsigned)(NBOX - 1 - i);
        }
    }
    __syncthreads();
    const int V = (int)sVCtr;

    if (tid < 256) {                             // suffix counts suf[t] = sum hist[t..255]
        unsigned sum = 0;
        for (int bb = tid; bb < 256; bb++) sum += hist[bb];
        suf[tid] = sum;
    }
    if (tid == 0) suf[256] = 0u;

    // ---- band loop: highest bins first; exact global descending order ----
    for (int iter = 0; iter < 260; ++iter) {
        __syncthreads();
        int cnt = sCnt, binHi = sBinHi;
        if (V == 0 || cnt >= MAXP || binHi < 0) break;

        if (tid == 0) {
            unsigned tail = suf[binHi + 1];
            int lo = 0;
            if (suf[0] - tail >= TARGET) {       // largest lo with band count >= TARGET
                int L = 0, R = binHi;
                while (L < R) {
                    int m = (L + R + 1) >> 1;
                    if (suf[m] - tail >= TARGET) L = m; else R = m - 1;
                }
                lo = L;
            }
            sBinLo = lo;
            sSelN  = (int)(suf[lo] - tail);
            sSelCtr = 0u;
        }
        __syncthreads();
        const int binLo = sBinLo, selN = sSelN;

        if (selN > 0) {
            // ---- band extraction ----
            if (iter == 0) {
                // in-place partition of the smem vlist: buffer reads in regs,
                // barrier, then scatter band members to skey[0..selN).
                unsigned long long r[4];
                #pragma unroll
                for (int t = 0; t < 4; ++t) {
                    int i = tid + t * NTHREADS;
                    r[t] = (i < V) ? skey[i] : 0ull;
                }
                __syncthreads();
                #pragma unroll
                for (int t = 0; t < 4; ++t) {
                    int i = tid + t * NTHREADS;
                    if (i < V) {
                        int bin = (int)score_bin((unsigned)(r[t] >> 32));
                        if (bin >= binLo && bin <= binHi) {
                            unsigned p = atomicAdd(&sSelCtr, 1u);
                            skey[p] = r[t];
                        }
                    }
                }
            } else {
                // vlist destroyed by earlier band: rescan global (rare path)
                for (int i = tid; i < NBOX; i += NTHREADS) {
                    float s = __ldg(&cls[i * 2 + 1]);
                    if (s > 0.5f) {
                        unsigned sb = __float_as_uint(s);
                        int bin = (int)score_bin(sb);
                        if (bin >= binLo && bin <= binHi) {
                            unsigned p = atomicAdd(&sSelCtr, 1u);
                            skey[p] = ((unsigned long long)sb << 32) | (unsigned)(NBOX - 1 - i);
                        }
                    }
                }
            }
            __syncthreads();

            const bool useBuf = (selN <= 1024);
            if (useBuf) {
                // ---- hybrid register/shfl bitonic, parametric S, descending ----
                int S = 32; while (S < selN) S <<= 1;
                for (int i = tid; i < S; i += NTHREADS)
                    if (i >= selN) skey[i] = 0ull;   // zero sinks to the end
                __syncthreads();

                unsigned long long x = 0ull;
                if (tid < S) {
                    x = skey[tid];
                    #pragma unroll
                    for (int k = 2; k <= 32; k <<= 1) {
                        #pragma unroll
                        for (int j = k >> 1; j > 0; j >>= 1) {
                            unsigned long long y = __shfl_xor_sync(0xffffffffu, x, j);
                            bool up      = ((tid & k) != 0);
                            bool lower   = ((tid & j) == 0);
                            bool wantMin = (lower == up);
                            if (wantMin ? (y < x) : (y > x)) x = y;
                        }
                    }
                    skey[tid] = x;
                }
                __syncthreads();

                for (int k = 64; k <= S; k <<= 1) {
                    for (int j = k >> 1; j >= 32; j >>= 1) {
                        if (tid < S) {
                            int i = tid, ixj = i ^ j;
                            if (ixj > i) {
                                unsigned long long ka = skey[i], kb = skey[ixj];
                                bool beforeBA = (kb > ka);
                                bool dir = ((i & k) == 0);
                                if (beforeBA == dir) { skey[i] = kb; skey[ixj] = ka; }
                            }
                        }
                        __syncthreads();
                    }
                    if (tid < S) {
                        x = skey[tid];
                        #pragma unroll
                        for (int j = 16; j > 0; j >>= 1) {
                            unsigned long long y = __shfl_xor_sync(0xffffffffu, x, j);
                            bool up      = ((tid & k) != 0);
                            bool lower   = ((tid & j) == 0);
                            bool wantMin = (lower == up);
                            if (wantMin ? (y < x) : (y > x)) x = y;
                        }
                        skey[tid] = x;
                    }
                    __syncthreads();
                }

                // ---- one parallel gather of all band boxes into smem ----
                for (int i = tid; i < selN; i += NTHREADS) {
                    int oi = NBOX - 1 - (int)(unsigned)(skey[i] & 0xFFFFFFFFull);
                    float4 bb = *(const float4*)(prop + (size_t)oi * 4);
                    bbuf[i] = bb;
                    abuf[i] = __fmul_rn(bb.z - bb.x, bb.w - bb.y);
                }
            } else {
                // ---- fallback: full smem bitonic (oversized tie band) ----
                int S = 1; while (S < selN) S <<= 1;
                for (int i = tid; i < S; i += NTHREADS)
                    if (i >= selN) skey[i] = 0ull;
                __syncthreads();
                for (int k = 2; k <= S; k <<= 1) {
                    for (int j = k >> 1; j > 0; j >>= 1) {
                        for (int i = tid; i < S; i += NTHREADS) {
                            int ixj = i ^ j;
                            if (ixj > i) {
                                unsigned long long ka = skey[i], kb = skey[ixj];
                                bool beforeBA = (kb > ka);
                                bool dir = ((i & k) == 0);
                                if (beforeBA == dir) { skey[i] = kb; skey[ixj] = ka; }
                            }
                        }
                        __syncthreads();
                    }
                }
            }
            if (tid < CHUNK) { chMaskLo[tid] = 0u; chMaskHi[tid] = 0u; }
            if (tid < 2) supMask[tid] = 0u;
            __syncthreads();

            // ---- chunk-parallel greedy NMS over this band ----
            for (int base = 0; base < selN; base += CHUNK) {
                int c0 = sCnt;                       // barrier-protected uniform read
                if (c0 >= MAXP) break;
                const int chunkN = (selN - base < CHUNK) ? (selN - base) : CHUNK;

                const float4* cB;
                const float*  cA;
                if (useBuf) {
                    cB = bbuf + base;
                    cA = abuf + base;
                } else {
                    if (tid < chunkN) {              // fallback staging from global
                        int oi = NBOX - 1 - (int)(unsigned)(skey[base + tid] & 0xFFFFFFFFull);
                        float4 bb = *(const float4*)(prop + (size_t)oi * 4);
                        cb[tid]  = bb;
                        car[tid] = __fmul_rn(bb.z - bb.x, bb.w - bb.y);
                    }
                    __syncthreads();
                    cB = cb;
                    cA = car;
                }

                // chunk vs already-kept
                for (int p = tid; p < CHUNK * c0; p += NTHREADS) {
                    int c = p & (CHUNK - 1);
                    int t = p >> 6;
                    if (c < chunkN && iou_ge(cB[c], cA[c], kbox[t], karea[t]))
                        atomicOr(&supMask[c >> 5], 1u << (c & 31));
                }
                // within-chunk pairwise (i suppresses j>i if i kept)
                for (int p = tid; p < CHUNK * CHUNK; p += NTHREADS) {
                    int i = p >> 6, j = p & (CHUNK - 1);
                    if (j > i && j < chunkN) {
                        if (iou_ge(cB[i], cA[i], cB[j], cA[j])) {
                            if (j < 32) atomicOr(&chMaskLo[i], 1u << j);
                            else        atomicOr(&chMaskHi[i], 1u << (j - 32));
                        }
                    }
                }
                __syncthreads();

                // ---- warp-uniform shfl resolve (warp 0) + parallel append;
                //      also clears masks for the next chunk ----
                if (tid < 32) {
                    unsigned long long m64a =
                        ((unsigned long long)chMaskHi[tid] << 32) | chMaskLo[tid];
                    unsigned long long m64b =
                        ((unsigned long long)chMaskHi[tid + 32] << 32) | chMaskLo[tid + 32];
                    unsigned long long sup =
                        ((unsigned long long)supMask[1] << 32) | supMask[0];
                    unsigned long long kept = 0ull;
                    int c2 = c0;
                    for (int c = 0; c < chunkN; ++c) {
                        if (!((sup >> c) & 1ull)) {
                            kept |= 1ull << c;
                            c2++;
                            unsigned long long m = (c < 32)
                                ? __shfl_sync(0xffffffffu, m64a, c)
                                : __shfl_sync(0xffffffffu, m64b, c - 32);
                            sup |= m;
                            if (c2 >= MAXP) break;   // 300th kept, stop
                        }
                    }
                    #pragma unroll
                    for (int h = 0; h < 2; ++h) {
                        int c = tid + h * 32;
                        if (c < chunkN && ((kept >> c) & 1ull)) {
                            int slot = c0 + __popcll(kept & ((1ull << c) - 1ull));
                            kbox[slot]  = cB[c];
                            karea[slot] = cA[c];
                            kidx[slot]  = NBOX - 1 -
                                (int)(unsigned)(skey[base + c] & 0xFFFFFFFFull);
                        }
                    }
                    chMaskLo[tid] = 0u; chMaskHi[tid] = 0u;
                    chMaskLo[tid + 32] = 0u; chMaskHi[tid + 32] = 0u;
                    if (tid < 2) supMask[tid] = 0u;
                    if (tid == 0) sCnt = c2;
                }
                __syncthreads();
            }
        }
        if (tid == 0) sBinHi = binLo - 1;
    }

    __syncthreads();
    // ---- epilogue: pad with last kept; nk==0 (<=> V==0) -> order[n-1] = 4095 ----
    const int nk = sCnt;
    float* outBoxes  = out;                              // [16,300,4]
    float* outScores = out + (size_t)BATCH * MAXP * 4;   // [16,300]
    for (int k = tid; k < MAXP; k += NTHREADS) {
        float4 bb; int sel;
        if (nk == 0) {
            sel = NBOX - 1;
            bb = *(const float4*)(prop + (size_t)sel * 4);
        } else {
            int kk = k < nk ? k : nk - 1;
            bb = kbox[kk];
            sel = kidx[kk];
        }
        *(float4*)(outBoxes + ((size_t)b * MAXP + k) * 4) = bb;
        outScores[(size_t)b * MAXP + k] = __ldg(&cls[sel * 2 + 1]);
    }
}

extern "C" void kernel_launch(void* const* d_in, const int* in_sizes, int n_in,
                              void* d_out, int out_size)
{
    const float* proposals = (const float*)d_in[0];   // [16,4096,4] f32
    const float* cls       = (const float*)d_in[1];   // [16,4096,2] f32
    float* out             = (float*)d_out;           // boxes then scores

    nms_kernel<<<BATCH, NTHREADS>>>(proposals, cls, out);
}

// round 11
// speedup vs baseline: 11.6257x; 1.2266x over previous
#include <cuda_runtime.h>

#define NBOX 4096
#define BATCH 16
#define MAXP 300
#define KEPT_PAD 304
#define NTHREADS 1024
#define CHUNK 64
#define TARGET 448

// IoU decision, bit-exact vs the reference's __fdiv_rn(inter,denom) >= 0.7f.
// Fast path: conservative multiply gates (denom > 0 always: denom >= max area).
// Only ratios inside (0.6998, 0.7002) fall through to the exact division, so
// MUFU (0.5 div/cyc/SM) stops being the kernel's binding resource.
__device__ __forceinline__ bool iou_ge(float4 a, float aa, float4 b, float ba)
{
    float ix1 = fmaxf(a.x, b.x);
    float iy1 = fmaxf(a.y, b.y);
    float ix2 = fminf(a.z, b.z);
    float iy2 = fminf(a.w, b.w);
    float w = fmaxf(ix2 - ix1, 0.0f);
    float h = fmaxf(iy2 - iy1, 0.0f);
    float inter = __fmul_rn(w, h);
    float denom = (aa + ba) - inter;
    float hi = __fmul_rn(0.7002f, denom);
    if (inter >= hi) return true;                 // ratio > 0.7000 -> RN(q) >= 0.7f
    float lo = __fmul_rn(0.6998f, denom);
    if (inter <= lo) return false;                // ratio < 0.6999 -> RN(q) <  0.7f
    return __fdiv_rn(inter, denom) >= 0.7f;       // borderline: exact
}

// Fixed monotone binning for scores > 0.5 (clamped; monotone non-decreasing).
__device__ __forceinline__ unsigned score_bin(unsigned sb)
{
    unsigned d = (sb - 0x3F000000u) >> 15;
    return d > 255u ? 255u : d;
}

__global__ __launch_bounds__(NTHREADS, 1)
void nms_kernel(const float* __restrict__ proposals,
                const float* __restrict__ cls_scores,
                float* __restrict__ out)
{
    __shared__ unsigned long long skey[NBOX];   // [0..V) vlist, then sorted band [0..S)
    __shared__ unsigned int hist[256];
    __shared__ unsigned int suf[257];
    __shared__ float4 kbox[KEPT_PAD];
    __shared__ float  karea[KEPT_PAD];
    __shared__ int    kidx[KEPT_PAD];
    __shared__ float4 cb[CHUNK];                // fallback staging only
    __shared__ float  car[CHUNK];
    __shared__ unsigned int chMaskLo[CHUNK];
    __shared__ unsigned int chMaskHi[CHUNK];
    __shared__ unsigned int supMask[2];
    __shared__ unsigned int sVCtr, sSelCtr;
    __shared__ int sCnt, sBinHi, sBinLo, sSelN;

    // Band box cache carved out of skey's tail (only used when selN <= 1024;
    // sorted keys then occupy skey[0..1023], no overlap).
    float4* bbuf = (float4*)(skey + 1024);      // 1024 * 16B = skey[1024..3071]
    float*  abuf = (float*)(skey + 3072);       // 1024 * 4B  = skey[3072..3583]

    const int b   = blockIdx.x;
    const int tid = threadIdx.x;
    const float* cls  = cls_scores + (size_t)b * NBOX * 2;
    const float* prop = proposals  + (size_t)b * NBOX * 4;

    if (tid == 0) { sVCtr = 0u; sCnt = 0; sBinHi = 255; }
    if (tid < 256) hist[tid] = 0u;
    __syncthreads();

    // ---- phase 0 (fused): validity + histogram + compacted vlist in smem ----
    for (int i = tid; i < NBOX; i += NTHREADS) {
        float s = __ldg(&cls[i * 2 + 1]);
        if (s > 0.5f) {                          // exact strict compare
            unsigned sb = __float_as_uint(s);
            atomicAdd(&hist[score_bin(sb)], 1u);
            unsigned p = atomicAdd(&sVCtr, 1u);
            skey[p] = ((unsigned long long)sb << 32) | (unsigned)(NBOX - 1 - i);
        }
    }
    __syncthreads();
    const int V = (int)sVCtr;

    if (tid < 256) {                             // suffix counts suf[t] = sum hist[t..255]
        unsigned sum = 0;
        for (int bb = tid; bb < 256; bb++) sum += hist[bb];
        suf[tid] = sum;
    }
    if (tid == 0) suf[256] = 0u;

    // ---- band loop: highest bins first; exact global descending order ----
    for (int iter = 0; iter < 260; ++iter) {
        __syncthreads();
        int cnt = sCnt, binHi = sBinHi;
        if (V == 0 || cnt >= MAXP || binHi < 0) break;

        if (tid == 0) {
            unsigned tail = suf[binHi + 1];
            int lo = 0;
            if (suf[0] - tail >= TARGET) {       // largest lo with band count >= TARGET
                int L = 0, R = binHi;
                while (L < R) {
                    int m = (L + R + 1) >> 1;
                    if (suf[m] - tail >= TARGET) L = m; else R = m - 1;
                }
                lo = L;
            }
            sBinLo = lo;
            sSelN  = (int)(suf[lo] - tail);
            sSelCtr = 0u;
        }
        __syncthreads();
        const int binLo = sBinLo, selN = sSelN;

        if (selN > 0) {
            // ---- band extraction ----
            if (iter == 0) {
                // in-place partition of the smem vlist: buffer reads in regs,
                // barrier, then scatter band members to skey[0..selN).
                unsigned long long r[4];
                #pragma unroll
                for (int t = 0; t < 4; ++t) {
                    int i = tid + t * NTHREADS;
                    r[t] = (i < V) ? skey[i] : 0ull;
                }
                __syncthreads();
                #pragma unroll
                for (int t = 0; t < 4; ++t) {
                    int i = tid + t * NTHREADS;
                    if (i < V) {
                        int bin = (int)score_bin((unsigned)(r[t] >> 32));
                        if (bin >= binLo && bin <= binHi) {
                            unsigned p = atomicAdd(&sSelCtr, 1u);
                            skey[p] = r[t];
                        }
                    }
                }
            } else {
                // vlist destroyed by earlier band: rescan global (rare path)
                for (int i = tid; i < NBOX; i += NTHREADS) {
                    float s = __ldg(&cls[i * 2 + 1]);
                    if (s > 0.5f) {
                        unsigned sb = __float_as_uint(s);
                        int bin = (int)score_bin(sb);
                        if (bin >= binLo && bin <= binHi) {
                            unsigned p = atomicAdd(&sSelCtr, 1u);
                            skey[p] = ((unsigned long long)sb << 32) | (unsigned)(NBOX - 1 - i);
                        }
                    }
                }
            }
            __syncthreads();

            const bool useBuf = (selN <= 1024);
            if (useBuf) {
                // ---- hybrid register/shfl bitonic, parametric S, descending ----
                int S = 32; while (S < selN) S <<= 1;
                for (int i = tid; i < S; i += NTHREADS)
                    if (i >= selN) skey[i] = 0ull;   // zero sinks to the end
                __syncthreads();

                unsigned long long x = 0ull;
                if (tid < S) {
                    x = skey[tid];
                    #pragma unroll
                    for (int k = 2; k <= 32; k <<= 1) {
                        #pragma unroll
                        for (int j = k >> 1; j > 0; j >>= 1) {
                            unsigned long long y = __shfl_xor_sync(0xffffffffu, x, j);
                            bool up      = ((tid & k) != 0);
                            bool lower   = ((tid & j) == 0);
                            bool wantMin = (lower == up);
                            if (wantMin ? (y < x) : (y > x)) x = y;
                        }
                    }
                    skey[tid] = x;
                }
                __syncthreads();

                for (int k = 64; k <= S; k <<= 1) {
                    for (int j = k >> 1; j >= 32; j >>= 1) {
                        if (tid < S) {
                            int i = tid, ixj = i ^ j;
                            if (ixj > i) {
                                unsigned long long ka = skey[i], kb = skey[ixj];
                                bool beforeBA = (kb > ka);
                                bool dir = ((i & k) == 0);
                                if (beforeBA == dir) { skey[i] = kb; skey[ixj] = ka; }
                            }
                        }
                        __syncthreads();
                    }
                    if (tid < S) {
                        x = skey[tid];
                        #pragma unroll
                        for (int j = 16; j > 0; j >>= 1) {
                            unsigned long long y = __shfl_xor_sync(0xffffffffu, x, j);
                            bool up      = ((tid & k) != 0);
                            bool lower   = ((tid & j) == 0);
                            bool wantMin = (lower == up);
                            if (wantMin ? (y < x) : (y > x)) x = y;
                        }
                        skey[tid] = x;
                    }
                    __syncthreads();
                }

                // ---- one parallel gather of all band boxes into smem ----
                for (int i = tid; i < selN; i += NTHREADS) {
                    int oi = NBOX - 1 - (int)(unsigned)(skey[i] & 0xFFFFFFFFull);
                    float4 bb = *(const float4*)(prop + (size_t)oi * 4);
                    bbuf[i] = bb;
                    abuf[i] = __fmul_rn(bb.z - bb.x, bb.w - bb.y);
                }
            } else {
                // ---- fallback: full smem bitonic (oversized tie band) ----
                int S = 1; while (S < selN) S <<= 1;
                for (int i = tid; i < S; i += NTHREADS)
                    if (i >= selN) skey[i] = 0ull;
                __syncthreads();
                for (int k = 2; k <= S; k <<= 1) {
                    for (int j = k >> 1; j > 0; j >>= 1) {
                        for (int i = tid; i < S; i += NTHREADS) {
                            int ixj = i ^ j;
                            if (ixj > i) {
                                unsigned long long ka = skey[i], kb = skey[ixj];
                                bool beforeBA = (kb > ka);
                                bool dir = ((i & k) == 0);
                                if (beforeBA == dir) { skey[i] = kb; skey[ixj] = ka; }
                            }
                        }
                        __syncthreads();
                    }
                }
            }
            if (tid < CHUNK) { chMaskLo[tid] = 0u; chMaskHi[tid] = 0u; }
            if (tid < 2) supMask[tid] = 0u;
            __syncthreads();

            // ---- chunk-parallel greedy NMS over this band ----
            for (int base = 0; base < selN; base += CHUNK) {
                int c0 = sCnt;                       // barrier-protected uniform read
                if (c0 >= MAXP) break;
                const int chunkN = (selN - base < CHUNK) ? (selN - base) : CHUNK;

                const float4* cB;
                const float*  cA;
                if (useBuf) {
                    cB = bbuf + base;
                    cA = abuf + base;
                } else {
                    if (tid < chunkN) {              // fallback staging from global
                        int oi = NBOX - 1 - (int)(unsigned)(skey[base + tid] & 0xFFFFFFFFull);
                        float4 bb = *(const float4*)(prop + (size_t)oi * 4);
                        cb[tid]  = bb;
                        car[tid] = __fmul_rn(bb.z - bb.x, bb.w - bb.y);
                    }
                    __syncthreads();
                    cB = cb;
                    cA = car;
                }

                // chunk vs already-kept
                for (int p = tid; p < CHUNK * c0; p += NTHREADS) {
                    int c = p & (CHUNK - 1);
                    int t = p >> 6;
                    if (c < chunkN && iou_ge(cB[c], cA[c], kbox[t], karea[t]))
                        atomicOr(&supMask[c >> 5], 1u << (c & 31));
                }
                // within-chunk pairwise (i suppresses j>i if i kept)
                for (int p = tid; p < CHUNK * CHUNK; p += NTHREADS) {
                    int i = p >> 6, j = p & (CHUNK - 1);
                    if (j > i && j < chunkN) {
                        if (iou_ge(cB[i], cA[i], cB[j], cA[j])) {
                            if (j < 32) atomicOr(&chMaskLo[i], 1u << j);
                            else        atomicOr(&chMaskHi[i], 1u << (j - 32));
                        }
                    }
                }
                __syncthreads();

                // ---- warp-uniform shfl resolve (warp 0) + parallel append;
                //      also clears masks for the next chunk ----
                if (tid < 32) {
                    unsigned long long m64a =
                        ((unsigned long long)chMaskHi[tid] << 32) | chMaskLo[tid];
                    unsigned long long m64b =
                        ((unsigned long long)chMaskHi[tid + 32] << 32) | chMaskLo[tid + 32];
                    unsigned long long sup =
                        ((unsigned long long)supMask[1] << 32) | supMask[0];
                    unsigned long long kept = 0ull;
                    int c2 = c0;
                    for (int c = 0; c < chunkN; ++c) {
                        if (!((sup >> c) & 1ull)) {
                            kept |= 1ull << c;
                            c2++;
                            unsigned long long m = (c < 32)
                                ? __shfl_sync(0xffffffffu, m64a, c)
                                : __shfl_sync(0xffffffffu, m64b, c - 32);
                            sup |= m;
                            if (c2 >= MAXP) break;   // 300th kept, stop
                        }
                    }
                    #pragma unroll
                    for (int h = 0; h < 2; ++h) {
                        int c = tid + h * 32;
                        if (c < chunkN && ((kept >> c) & 1ull)) {
                            int slot = c0 + __popcll(kept & ((1ull << c) - 1ull));
                            kbox[slot]  = cB[c];
                            karea[slot] = cA[c];
                            kidx[slot]  = NBOX - 1 -
                                (int)(unsigned)(skey[base + c] & 0xFFFFFFFFull);
                        }
                    }
                    chMaskLo[tid] = 0u; chMaskHi[tid] = 0u;
                    chMaskLo[tid + 32] = 0u; chMaskHi[tid + 32] = 0u;
                    if (tid < 2) supMask[tid] = 0u;
                    if (tid == 0) sCnt = c2;
                }
                __syncthreads();
            }
        }
        if (tid == 0) sBinHi = binLo - 1;
    }

    __syncthreads();
    // ---- epilogue: pad with last kept; nk==0 (<=> V==0) -> order[n-1] = 4095 ----
    const int nk = sCnt;
    float* outBoxes  = out;                              // [16,300,4]
    float* outScores = out + (size_t)BATCH * MAXP * 4;   // [16,300]
    for (int k = tid; k < MAXP; k += NTHREADS) {
        float4 bb; int sel;
        if (nk == 0) {
            sel = NBOX - 1;
            bb = *(const float4*)(prop + (size_t)sel * 4);
        } else {
            int kk = k < nk ? k : nk - 1;
            bb = kbox[kk];
            sel = kidx[kk];
        }
        *(float4*)(outBoxes + ((size_t)b * MAXP + k) * 4) = bb;
        outScores[(size_t)b * MAXP + k] = __ldg(&cls[sel * 2 + 1]);
    }
}

extern "C" void kernel_launch(void* const* d_in, const int* in_sizes, int n_in,
                              void* d_out, int out_size)
{
    const float* proposals = (const float*)d_in[0];   // [16,4096,4] f32
    const float* cls       = (const float*)d_in[1];   // [16,4096,2] f32
    float* out             = (float*)d_out;           // boxes then scores

    nms_kernel<<<BATCH, NTHREADS>>>(proposals, cls, out);
}

// round 12
// speedup vs baseline: 12.6466x; 1.0878x over previous
#include <cuda_runtime.h>

#define NBOX 4096
#define BATCH 16
#define MAXP 300
#define KEPT_PAD 304
#define NTHREADS 1024
#define CHUNK 64
#define TARGET 320

// IoU decision, bit-exact vs the reference's __fdiv_rn(inter,denom) >= 0.7f.
// Conservative multiply gates; only ratios in (0.6998, 0.7002) take the div.
__device__ __forceinline__ bool iou_ge(float4 a, float aa, float4 b, float ba)
{
    float ix1 = fmaxf(a.x, b.x);
    float iy1 = fmaxf(a.y, b.y);
    float ix2 = fminf(a.z, b.z);
    float iy2 = fminf(a.w, b.w);
    float w = fmaxf(ix2 - ix1, 0.0f);
    float h = fmaxf(iy2 - iy1, 0.0f);
    float inter = __fmul_rn(w, h);
    float denom = (aa + ba) - inter;
    if (inter >= __fmul_rn(0.7002f, denom)) return true;
    if (inter <= __fmul_rn(0.6998f, denom)) return false;
    return __fdiv_rn(inter, denom) >= 0.7f;       // borderline: exact
}

// Fixed monotone binning for scores > 0.5 (clamped; monotone non-decreasing).
__device__ __forceinline__ unsigned score_bin(unsigned sb)
{
    unsigned d = (sb - 0x3F000000u) >> 15;
    return d > 255u ? 255u : d;
}

__global__ __launch_bounds__(NTHREADS, 1)
void nms_kernel(const float* __restrict__ proposals,
                const float* __restrict__ cls_scores,
                float* __restrict__ out)
{
    __shared__ unsigned long long skey[NBOX];   // [0..V) vlist, then sorted band [0..S)
    __shared__ unsigned int hist[256];
    __shared__ unsigned int suf[257];
    __shared__ float4 kbox[KEPT_PAD];
    __shared__ float  karea[KEPT_PAD];
    __shared__ int    kidx[KEPT_PAD];
    __shared__ float4 cb[CHUNK];                // fallback staging only
    __shared__ float  car[CHUNK];
    __shared__ unsigned int chMaskLo[CHUNK];
    __shared__ unsigned int chMaskHi[CHUNK];
    __shared__ unsigned int supMask[2];
    __shared__ unsigned int sVCtr, sSelCtr;
    __shared__ int sCnt, sBinHi, sBinLo, sSelN;

    // Band box cache carved out of skey's tail (selN <= 1024 path only;
    // sorted keys occupy skey[0..1023], no overlap).
    float4* bbuf = (float4*)(skey + 1024);      // skey[1024..3071]
    float*  abuf = (float*)(skey + 3072);       // skey[3072..3583]

    const int b   = blockIdx.x;
    const int tid = threadIdx.x;
    const float* cls  = cls_scores + (size_t)b * NBOX * 2;
    const float* prop = proposals  + (size_t)b * NBOX * 4;

    if (tid == 0) { sVCtr = 0u; sCnt = 0; sBinHi = 255; }
    if (tid < 256) hist[tid] = 0u;
    __syncthreads();

    // ---- phase 0 (fused): validity + histogram + compacted vlist in smem ----
    for (int i = tid; i < NBOX; i += NTHREADS) {
        float s = __ldg(&cls[i * 2 + 1]);
        if (s > 0.5f) {                          // exact strict compare
            unsigned sb = __float_as_uint(s);
            atomicAdd(&hist[score_bin(sb)], 1u);
            unsigned p = atomicAdd(&sVCtr, 1u);
            skey[p] = ((unsigned long long)sb << 32) | (unsigned)(NBOX - 1 - i);
        }
    }
    __syncthreads();
    const int V = (int)sVCtr;

    if (tid < 256) {                             // suffix counts suf[t] = sum hist[t..255]
        unsigned sum = 0;
        for (int bb = tid; bb < 256; bb++) sum += hist[bb];
        suf[tid] = sum;
    }
    if (tid == 0) suf[256] = 0u;

    // ---- band loop: highest bins first; exact global descending order ----
    for (int iter = 0; iter < 260; ++iter) {
        __syncthreads();
        int cnt = sCnt, binHi = sBinHi;
        if (V == 0 || cnt >= MAXP || binHi < 0) break;

        if (tid == 0) {
            unsigned tail = suf[binHi + 1];
            int lo = 0;
            if (suf[0] - tail >= TARGET) {       // largest lo with band count >= TARGET
                int L = 0, R = binHi;
                while (L < R) {
                    int m = (L + R + 1) >> 1;
                    if (suf[m] - tail >= TARGET) L = m; else R = m - 1;
                }
                lo = L;
            }
            sBinLo = lo;
            sSelN  = (int)(suf[lo] - tail);
            sSelCtr = 0u;
        }
        __syncthreads();
        const int binLo = sBinLo, selN = sSelN;

        if (selN > 0) {
            // ---- band extraction ----
            if (iter == 0) {
                unsigned long long r[4];
                #pragma unroll
                for (int t = 0; t < 4; ++t) {
                    int i = tid + t * NTHREADS;
                    r[t] = (i < V) ? skey[i] : 0ull;
                }
                __syncthreads();
                #pragma unroll
                for (int t = 0; t < 4; ++t) {
                    int i = tid + t * NTHREADS;
                    if (i < V) {
                        int bin = (int)score_bin((unsigned)(r[t] >> 32));
                        if (bin >= binLo && bin <= binHi) {
                            unsigned p = atomicAdd(&sSelCtr, 1u);
                            skey[p] = r[t];
                        }
                    }
                }
            } else {
                for (int i = tid; i < NBOX; i += NTHREADS) {
                    float s = __ldg(&cls[i * 2 + 1]);
                    if (s > 0.5f) {
                        unsigned sb = __float_as_uint(s);
                        int bin = (int)score_bin(sb);
                        if (bin >= binLo && bin <= binHi) {
                            unsigned p = atomicAdd(&sSelCtr, 1u);
                            skey[p] = ((unsigned long long)sb << 32) | (unsigned)(NBOX - 1 - i);
                        }
                    }
                }
            }
            __syncthreads();

            const bool useBuf = (selN <= 1024);
            if (useBuf) {
                // ---- hybrid register/shfl bitonic, parametric S, descending ----
                int S = 32; while (S < selN) S <<= 1;
                for (int i = tid; i < S; i += NTHREADS)
                    if (i >= selN) skey[i] = 0ull;   // zero sinks to the end
                __syncthreads();

                unsigned long long x = 0ull;
                if (tid < S) {
                    x = skey[tid];
                    #pragma unroll
                    for (int k = 2; k <= 32; k <<= 1) {
                        #pragma unroll
                        for (int j = k >> 1; j > 0; j >>= 1) {
                            unsigned long long y = __shfl_xor_sync(0xffffffffu, x, j);
                            bool up      = ((tid & k) != 0);
                            bool lower   = ((tid & j) == 0);
                            bool wantMin = (lower == up);
                            if (wantMin ? (y < x) : (y > x)) x = y;
                        }
                    }
                    skey[tid] = x;
                }
                __syncthreads();

                for (int k = 64; k <= S; k <<= 1) {
                    for (int j = k >> 1; j >= 32; j >>= 1) {
                        if (tid < S) {
                            int i = tid, ixj = i ^ j;
                            if (ixj > i) {
                                unsigned long long ka = skey[i], kb = skey[ixj];
                                bool beforeBA = (kb > ka);
                                bool dir = ((i & k) == 0);
                                if (beforeBA == dir) { skey[i] = kb; skey[ixj] = ka; }
                            }
                        }
                        __syncthreads();
                    }
                    if (tid < S) {
                        x = skey[tid];
                        #pragma unroll
                        for (int j = 16; j > 0; j >>= 1) {
                            unsigned long long y = __shfl_xor_sync(0xffffffffu, x, j);
                            bool up      = ((tid & k) != 0);
                            bool lower   = ((tid & j) == 0);
                            bool wantMin = (lower == up);
                            if (wantMin ? (y < x) : (y > x)) x = y;
                        }
                        skey[tid] = x;
                    }
                    __syncthreads();
                }

                // ---- one parallel gather of all band boxes into smem ----
                for (int i = tid; i < selN; i += NTHREADS) {
                    int oi = NBOX - 1 - (int)(unsigned)(skey[i] & 0xFFFFFFFFull);
                    float4 bb = *(const float4*)(prop + (size_t)oi * 4);
                    bbuf[i] = bb;
                    abuf[i] = __fmul_rn(bb.z - bb.x, bb.w - bb.y);
                }
            } else {
                // ---- fallback: full smem bitonic (oversized tie band) ----
                int S = 1; while (S < selN) S <<= 1;
                for (int i = tid; i < S; i += NTHREADS)
                    if (i >= selN) skey[i] = 0ull;
                __syncthreads();
                for (int k = 2; k <= S; k <<= 1) {
                    for (int j = k >> 1; j > 0; j >>= 1) {
                        for (int i = tid; i < S; i += NTHREADS) {
                            int ixj = i ^ j;
                            if (ixj > i) {
                                unsigned long long ka = skey[i], kb = skey[ixj];
                                bool beforeBA = (kb > ka);
                                bool dir = ((i & k) == 0);
                                if (beforeBA == dir) { skey[i] = kb; skey[ixj] = ka; }
                            }
                        }
                        __syncthreads();
                    }
                }
            }
            if (tid < CHUNK) { chMaskLo[tid] = 0u; chMaskHi[tid] = 0u; }
            if (tid < 2) supMask[tid] = 0u;
            __syncthreads();

            // ---- chunk-parallel greedy NMS over this band ----
            for (int base = 0; base < selN; base += CHUNK) {
                int c0 = sCnt;                       // barrier-protected uniform read
                if (c0 >= MAXP) break;
                const int chunkN = (selN - base < CHUNK) ? (selN - base) : CHUNK;

                const float4* cB;
                const float*  cA;
                if (useBuf) {
                    cB = bbuf + base;
                    cA = abuf + base;
                } else {
                    if (tid < chunkN) {              // fallback staging from global
                        int oi = NBOX - 1 - (int)(unsigned)(skey[base + tid] & 0xFFFFFFFFull);
                        float4 bb = *(const float4*)(prop + (size_t)oi * 4);
                        cb[tid]  = bb;
                        car[tid] = __fmul_rn(bb.z - bb.x, bb.w - bb.y);
                    }
                    __syncthreads();
                    cB = cb;
                    cA = car;
                }

                // chunk vs already-kept: c fixed per thread, stride over kept.
                {
                    const int c  = tid & (CHUNK - 1);
                    const int t0 = tid >> 6;         // 0..15
                    bool sup = false;
                    if (c < chunkN) {
                        const float4 cc = cB[c];
                        const float  ca = cA[c];
                        for (int t = t0; t < c0; t += 16) {
                            if (iou_ge(cc, ca, kbox[t], karea[t])) { sup = true; break; }
                        }
                    }
                    if (sup) atomicOr(&supMask[c >> 5], 1u << (c & 31));
                }
                // within-chunk pairwise: j fixed per thread (the suppressee),
                // i strided (the earlier candidate). IoU symmetric.
                {
                    const int j  = tid & (CHUNK - 1);
                    const int i0 = tid >> 6;         // 0..15
                    if (j < chunkN) {
                        const float4 cj = cB[j];
                        const float  aj = cA[j];
                        #pragma unroll
                        for (int h = 0; h < 4; ++h) {
                            int i = i0 + h * 16;
                            if (i < j && iou_ge(cj, aj, cB[i], cA[i])) {
                                if (j < 32) atomicOr(&chMaskLo[i], 1u << j);
                                else        atomicOr(&chMaskHi[i], 1u << (j - 32));
                            }
                        }
                    }
                }
                __syncthreads();

                // ---- warp-uniform shfl resolve (warp 0) + parallel append;
                //      also clears masks for the next chunk ----
                if (tid < 32) {
                    unsigned long long m64a =
                        ((unsigned long long)chMaskHi[tid] << 32) | chMaskLo[tid];
                    unsigned long long m64b =
                        ((unsigned long long)chMaskHi[tid + 32] << 32) | chMaskLo[tid + 32];
                    unsigned long long sup =
                        ((unsigned long long)supMask[1] << 32) | supMask[0];
                    unsigned long long kept = 0ull;
                    int c2 = c0;
                    for (int c = 0; c < chunkN; ++c) {
                        if (!((sup >> c) & 1ull)) {
                            kept |= 1ull << c;
                            c2++;
                            unsigned long long m = (c < 32)
                                ? __shfl_sync(0xffffffffu, m64a, c)
                                : __shfl_sync(0xffffffffu, m64b, c - 32);
                            sup |= m;
                            if (c2 >= MAXP) break;   // 300th kept, stop
                        }
                    }
                    #pragma unroll
                    for (int h = 0; h < 2; ++h) {
                        int c = tid + h * 32;
                        if (c < chunkN && ((kept >> c) & 1ull)) {
                            int slot = c0 + __popcll(kept & ((1ull << c) - 1ull));
                            kbox[slot]  = cB[c];
                            karea[slot] = cA[c];
                            kidx[slot]  = NBOX - 1 -
                                (int)(unsigned)(skey[base + c] & 0xFFFFFFFFull);
                        }
                    }
                    chMaskLo[tid] = 0u; chMaskHi[tid] = 0u;
                    chMaskLo[tid + 32] = 0u; chMaskHi[tid + 32] = 0u;
                    if (tid < 2) supMask[tid] = 0u;
                    if (tid == 0) sCnt = c2;
                }
                __syncthreads();
            }
        }
        if (tid == 0) sBinHi = binLo - 1;
    }

    __syncthreads();
    // ---- epilogue: pad with last kept; nk==0 (<=> V==0) -> order[n-1] = 4095 ----
    const int nk = sCnt;
    float* outBoxes  = out;                              // [16,300,4]
    float* outScores = out + (size_t)BATCH * MAXP * 4;   // [16,300]
    for (int k = tid; k < MAXP; k += NTHREADS) {
        float4 bb; int sel;
        if (nk == 0) {
            sel = NBOX - 1;
            bb = *(const float4*)(prop + (size_t)sel * 4);
        } else {
            int kk = k < nk ? k : nk - 1;
            bb = kbox[kk];
            sel = kidx[kk];
        }
        *(float4*)(outBoxes + ((size_t)b * MAXP + k) * 4) = bb;
        outScores[(size_t)b * MAXP + k] = __ldg(&cls[sel * 2 + 1]);
    }
}

extern "C" void kernel_launch(void* const* d_in, const int* in_sizes, int n_in,
                              void* d_out, int out_size)
{
    const float* proposals = (const float*)d_in[0];   // [16,4096,4] f32
    const float* cls       = (const float*)d_in[1];   // [16,4096,2] f32
    float* out             = (float*)d_out;           // boxes then scores

    nms_kernel<<<BATCH, NTHREADS>>>(proposals, cls, out);
}

// round 14
// speedup vs baseline: 21.3345x; 1.6870x over previous
#include <cuda_runtime.h>

#define NBOX 4096
#define BATCH 16
#define MAXP 300
#define KEPT_PAD 304
#define NTHREADS 1024
#define CHUNK 64
#define TARGET 320
#define FULLM 0xffffffffu

// IoU decision, bit-exact vs the reference's __fdiv_rn(inter,denom) >= 0.7f.
// Conservative multiply gates; only ratios in (0.6998, 0.7002) take the div.
__device__ __forceinline__ bool iou_ge(float4 a, float aa, float4 b, float ba)
{
    float ix1 = fmaxf(a.x, b.x);
    float iy1 = fmaxf(a.y, b.y);
    float ix2 = fminf(a.z, b.z);
    float iy2 = fminf(a.w, b.w);
    float w = fmaxf(ix2 - ix1, 0.0f);
    float h = fmaxf(iy2 - iy1, 0.0f);
    float inter = __fmul_rn(w, h);
    float denom = (aa + ba) - inter;
    if (inter >= __fmul_rn(0.7002f, denom)) return true;
    if (inter <= __fmul_rn(0.6998f, denom)) return false;
    return __fdiv_rn(inter, denom) >= 0.7f;       // borderline: exact
}

// Fixed monotone binning for scores > 0.5 (clamped; monotone non-decreasing).
__device__ __forceinline__ unsigned score_bin(unsigned sb)
{
    unsigned d = (sb - 0x3F000000u) >> 15;
    return d > 255u ? 255u : d;
}

// Warp-aggregated append of a valid element to skey[*ctr ...]; order-free.
__device__ __forceinline__ void warp_append(unsigned int* ctr,
                                            unsigned long long* buf,
                                            bool valid, unsigned long long key,
                                            int lane)
{
    unsigned m = __ballot_sync(FULLM, valid);
    if (!m) return;
    int leader = __ffs(m) - 1;
    unsigned basep = 0;
    if (lane == leader) basep = atomicAdd(ctr, (unsigned)__popc(m));
    basep = __shfl_sync(FULLM, basep, leader);
    if (valid) buf[basep + __popc(m & ((1u << lane) - 1u))] = key;
}

__global__ __launch_bounds__(NTHREADS, 1)
void nms_kernel(const float* __restrict__ proposals,
                const float* __restrict__ cls_scores,
                float* __restrict__ out)
{
    __shared__ unsigned long long skey[NBOX];   // [0..V) vlist, then sorted band [0..S)
    __shared__ unsigned int hist[256];
    __shared__ unsigned int suf[257];
    __shared__ float4 kbox[KEPT_PAD];
    __shared__ float  karea[KEPT_PAD];
    __shared__ int    kidx[KEPT_PAD];
    __shared__ float4 cb[CHUNK];                // fallback staging only
    __shared__ float  car[CHUNK];
    __shared__ unsigned int chMaskLo[CHUNK];
    __shared__ unsigned int chMaskHi[CHUNK];
    __shared__ unsigned int supMask[2];
    __shared__ unsigned int sVCtr, sSelCtr;
    __shared__ int sCnt, sBinHi, sBinLo, sSelN;

    // Band box cache carved out of skey's tail (selN <= 1024 path only).
    float4* bbuf = (float4*)(skey + 1024);      // skey[1024..3071]
    float*  abuf = (float*)(skey + 3072);       // skey[3072..3583]

    const int b    = blockIdx.x;
    const int tid  = threadIdx.x;
    const int lane = tid & 31;
    const float* cls  = cls_scores + (size_t)b * NBOX * 2;
    const float* prop = proposals  + (size_t)b * NBOX * 4;

    if (tid == 0) { sVCtr = 0u; sCnt = 0; sBinHi = 255; }
    if (tid < 256) hist[tid] = 0u;
    __syncthreads();

    // ---- phase 0 (fused): validity + histogram + compacted vlist in smem ----
    #pragma unroll
    for (int t = 0; t < NBOX / NTHREADS; ++t) {
        int i = tid + t * NTHREADS;
        float s = __ldg(&cls[i * 2 + 1]);
        bool valid = s > 0.5f;                   // exact strict compare
        unsigned sb = __float_as_uint(s);
        if (valid) atomicAdd(&hist[score_bin(sb)], 1u);
        warp_append(&sVCtr, skey, valid,
                    ((unsigned long long)sb << 32) | (unsigned)(NBOX - 1 - i), lane);
    }
    __syncthreads();
    const int V = (int)sVCtr;

    if (tid < 256) {                             // suffix counts suf[t] = sum hist[t..255]
        unsigned sum = 0;
        for (int bb = tid; bb < 256; bb++) sum += hist[bb];
        suf[tid] = sum;
    }
    if (tid == 0) suf[256] = 0u;

    // ---- band loop: highest bins first; exact global descending order ----
    for (int iter = 0; iter < 260; ++iter) {
        __syncthreads();
        int cnt = sCnt, binHi = sBinHi;
        if (V == 0 || cnt >= MAXP || binHi < 0) break;

        if (tid == 0) {
            unsigned tail = suf[binHi + 1];
            int lo = 0;
            if (suf[0] - tail >= TARGET) {       // largest lo with band count >= TARGET
                int L = 0, R = binHi;
                while (L < R) {
                    int m = (L + R + 1) >> 1;
                    if (suf[m] - tail >= TARGET) L = m; else R = m - 1;
                }
                lo = L;
            }
            sBinLo = lo;
            sSelN  = (int)(suf[lo] - tail);
            sSelCtr = 0u;
        }
        __syncthreads();
        const int binLo = sBinLo, selN = sSelN;

        if (selN > 0) {
            // ---- band extraction ----
            if (iter == 0) {
                unsigned long long r[4];
                #pragma unroll
                for (int t = 0; t < 4; ++t) {
                    int i = tid + t * NTHREADS;
                    r[t] = (i < V) ? skey[i] : 0ull;
                }
                __syncthreads();
                #pragma unroll
                for (int t = 0; t < 4; ++t) {
                    int i = tid + t * NTHREADS;
                    bool inband = false;
                    if (i < V) {
                        int bin = (int)score_bin((unsigned)(r[t] >> 32));
                        inband = (bin >= binLo && bin <= binHi);
                    }
                    warp_append(&sSelCtr, skey, inband, r[t], lane);
                }
            } else {
                #pragma unroll
                for (int t = 0; t < NBOX / NTHREADS; ++t) {
                    int i = tid + t * NTHREADS;
                    float s = __ldg(&cls[i * 2 + 1]);
                    bool inband = false;
                    unsigned sb = __float_as_uint(s);
                    if (s > 0.5f) {
                        int bin = (int)score_bin(sb);
                        inband = (bin >= binLo && bin <= binHi);
                    }
                    warp_append(&sSelCtr, skey, inband,
                                ((unsigned long long)sb << 32) | (unsigned)(NBOX - 1 - i),
                                lane);
                }
            }
            __syncthreads();

            const bool useBuf = (selN <= 1024);
            if (useBuf) {
                // ---- hybrid register/shfl bitonic, parametric S, descending ----
                int S = 32; while (S < selN) S <<= 1;
                for (int i = tid; i < S; i += NTHREADS)
                    if (i >= selN) skey[i] = 0ull;   // zero sinks to the end
                __syncthreads();

                unsigned long long x = 0ull;
                if (tid < S) {
                    x = skey[tid];
                    #pragma unroll
                    for (int k = 2; k <= 32; k <<= 1) {
                        #pragma unroll
                        for (int j = k >> 1; j > 0; j >>= 1) {
                            unsigned long long y = __shfl_xor_sync(FULLM, x, j);
                            bool up      = ((tid & k) != 0);
                            bool lower   = ((tid & j) == 0);
                            bool wantMin = (lower == up);
                            if (wantMin ? (y < x) : (y > x)) x = y;
                        }
                    }
                    skey[tid] = x;
                }
                __syncthreads();

                for (int k = 64; k <= S; k <<= 1) {
                    for (int j = k >> 1; j >= 32; j >>= 1) {
                        if (tid < S) {
                            int i = tid, ixj = i ^ j;
                            if (ixj > i) {
                                unsigned long long ka = skey[i], kb = skey[ixj];
                                bool beforeBA = (kb > ka);
                                bool dir = ((i & k) == 0);
                                if (beforeBA == dir) { skey[i] = kb; skey[ixj] = ka; }
                            }
                        }
                        __syncthreads();
                    }
                    if (tid < S) {
                        x = skey[tid];
                        #pragma unroll
                        for (int j = 16; j > 0; j >>= 1) {
                            unsigned long long y = __shfl_xor_sync(FULLM, x, j);
                            bool up      = ((tid & k) != 0);
                            bool lower   = ((tid & j) == 0);
                            bool wantMin = (lower == up);
                            if (wantMin ? (y < x) : (y > x)) x = y;
                        }
                        skey[tid] = x;
                    }
                    __syncthreads();
                }

                // ---- one parallel gather of all band boxes into smem ----
                for (int i = tid; i < selN; i += NTHREADS) {
                    int oi = NBOX - 1 - (int)(unsigned)(skey[i] & 0xFFFFFFFFull);
                    float4 bb = *(const float4*)(prop + (size_t)oi * 4);
                    bbuf[i] = bb;
                    abuf[i] = __fmul_rn(bb.z - bb.x, bb.w - bb.y);
                }
            } else {
                // ---- fallback: full smem bitonic (oversized tie band) ----
                int S = 1; while (S < selN) S <<= 1;
                for (int i = tid; i < S; i += NTHREADS)
                    if (i >= selN) skey[i] = 0ull;
                __syncthreads();
                for (int k = 2; k <= S; k <<= 1) {
                    for (int j = k >> 1; j > 0; j >>= 1) {
                        for (int i = tid; i < S; i += NTHREADS) {
                            int ixj = i ^ j;
                            if (ixj > i) {
                                unsigned long long ka = skey[i], kb = skey[ixj];
                                bool beforeBA = (kb > ka);
                                bool dir = ((i & k) == 0);
                                if (beforeBA == dir) { skey[i] = kb; skey[ixj] = ka; }
                            }
                        }
                        __syncthreads();
                    }
                }
            }
            if (tid < CHUNK) { chMaskLo[tid] = 0u; chMaskHi[tid] = 0u; }
            if (tid < 2) supMask[tid] = 0u;
            __syncthreads();

            // ---- chunk-parallel greedy NMS over this band ----
            for (int base = 0; base < selN; base += CHUNK) {
                int c0 = sCnt;                       // barrier-protected uniform read
                if (c0 >= MAXP) break;
                const int chunkN = (selN - base < CHUNK) ? (selN - base) : CHUNK;

                const float4* cB;
                const float*  cA;
                if (useBuf) {
                    cB = bbuf + base;
                    cA = abuf + base;
                } else {
                    if (tid < chunkN) {              // fallback staging from global
                        int oi = NBOX - 1 - (int)(unsigned)(skey[base + tid] & 0xFFFFFFFFull);
                        float4 bb = *(const float4*)(prop + (size_t)oi * 4);
                        cb[tid]  = bb;
                        car[tid] = __fmul_rn(bb.z - bb.x, bb.w - bb.y);
                    }
                    __syncthreads();
                    cB = cb;
                    cA = car;
                }

                // fused IoU dispatch: candidate c fixed per thread for both loops
                {
                    const int c  = tid & (CHUNK - 1);
                    const int t0 = tid >> 6;         // 0..15
                    if (c < chunkN) {
                        const float4 cc = cB[c];
                        const float  ca = cA[c];
                        // vs already-kept, strided
                        bool sup = false;
                        for (int t = t0; t < c0; t += 16) {
                            if (iou_ge(cc, ca, kbox[t], karea[t])) { sup = true; break; }
                        }
                        if (sup) atomicOr(&supMask[c >> 5], 1u << (c & 31));
                        // within-chunk: earlier candidate i vs this c (IoU symmetric)
                        #pragma unroll
                        for (int h = 0; h < 4; ++h) {
                            int i = t0 + h * 16;
                            if (i < c && iou_ge(cc, ca, cB[i], cA[i])) {
                                if (c < 32) atomicOr(&chMaskLo[i], 1u << c);
                                else        atomicOr(&chMaskHi[i], 1u << (c - 32));
                            }
                        }
                    }
                }
                __syncthreads();

                // ---- sparse resolve (warp 0): walk only nonzero-mask candidates ----
                if (tid < 32) {
                    unsigned long long m64a =
                        ((unsigned long long)chMaskHi[tid] << 32) | chMaskLo[tid];
                    unsigned long long m64b =
                        ((unsigned long long)chMaskHi[tid + 32] << 32) | chMaskLo[tid + 32];
                    unsigned long long sup =
                        ((unsigned long long)supMask[1] << 32) | supMask[0];
                    unsigned actLo = __ballot_sync(FULLM, m64a != 0ull);
                    unsigned actHi = __ballot_sync(FULLM, m64b != 0ull);
                    unsigned long long act =
                        ((unsigned long long)actHi << 32) | actLo;
                    while (act) {                    // typically 0-3 iterations
                        int c = __ffsll(act) - 1;
                        act &= act - 1ull;
                        if (!((sup >> c) & 1ull)) {
                            unsigned long long m = (c < 32)
                                ? __shfl_sync(FULLM, m64a, c)
                                : __shfl_sync(FULLM, m64b, c - 32);
                            sup |= m;
                        }
                    }
                    unsigned long long kept = ~sup;
                    if (chunkN < 64) kept &= (1ull << chunkN) - 1ull;
                    int limit = MAXP - c0;
                    int excess = __popcll(kept) - limit;
                    while (excess > 0) {             // truncate to lowest `limit` bits
                        kept &= ~(1ull << (63 - __clzll(kept)));
                        excess--;
                    }
                    int c2 = c0 + __popcll(kept);
                    #pragma unroll
                    for (int h = 0; h < 2; ++h) {
                        int c = tid + h * 32;
                        if (c < chunkN && ((kept >> c) & 1ull)) {
                            int slot = c0 + __popcll(kept & ((1ull << c) - 1ull));
                            kbox[slot]  = cB[c];
                            karea[slot] = cA[c];
                            kidx[slot]  = NBOX - 1 -
                                (int)(unsigned)(skey[base + c] & 0xFFFFFFFFull);
                        }
                    }
                    chMaskLo[tid] = 0u; chMaskHi[tid] = 0u;
                    chMaskLo[tid + 32] = 0u; chMaskHi[tid + 32] = 0u;
                    if (tid < 2) supMask[tid] = 0u;
                    if (tid == 0) sCnt = c2;
                }
                __syncthreads();
            }
        }
        if (tid == 0) sBinHi = binLo - 1;
    }

    __syncthreads();
    // ---- epilogue: pad with last kept; nk==0 (<=> V==0) -> order[n-1] = 4095 ----
    const int nk = sCnt;
    float* outBoxes  = out;                              // [16,300,4]
    float* outScores = out + (size_t)BATCH * MAXP * 4;   // [16,300]
    for (int k = tid; k < MAXP; k += NTHREADS) {
        float4 bb; int sel;
        if (nk == 0) {
            sel = NBOX - 1;
            bb = *(const float4*)(prop + (size_t)sel * 4);
        } else {
            int kk = k < nk ? k : nk - 1;
            bb = kbox[kk];
            sel = kidx[kk];
        }
        *(float4*)(outBoxes + ((size_t)b * MAXP + k) * 4) = bb;
        outScores[(size_t)b * MAXP + k] = __ldg(&cls[sel * 2 + 1]);
    }
}

extern "C" void kernel_launch(void* const* d_in, const int* in_sizes, int n_in,
                              void* d_out, int out_size)
{
    const float* proposals = (const float*)d_in[0];   // [16,4096,4] f32
    const float* cls       = (const float*)d_in[1];   // [16,4096,2] f32
    float* out             = (float*)d_out;           // boxes then scores

    nms_kernel<<<BATCH, NTHREADS>>>(proposals, cls, out);
}

// round 15
// speedup vs baseline: 21.6186x; 1.0133x over previous
#include <cuda_runtime.h>

#define NBOX 4096
#define BATCH 16
#define MAXP 300
#define KEPT_PAD 304
#define NTHREADS 1024
#define CHUNK 64
#define TARGET 320
#define RANKMAX 384
#define FULLM 0xffffffffu

// IoU decision, bit-exact vs the reference's __fdiv_rn(inter,denom) >= 0.7f.
// Conservative multiply gates; only ratios in (0.6998, 0.7002) take the div.
__device__ __forceinline__ bool iou_ge(float4 a, float aa, float4 b, float ba)
{
    float ix1 = fmaxf(a.x, b.x);
    float iy1 = fmaxf(a.y, b.y);
    float ix2 = fminf(a.z, b.z);
    float iy2 = fminf(a.w, b.w);
    float w = fmaxf(ix2 - ix1, 0.0f);
    float h = fmaxf(iy2 - iy1, 0.0f);
    float inter = __fmul_rn(w, h);
    float denom = (aa + ba) - inter;
    if (inter >= __fmul_rn(0.7002f, denom)) return true;
    if (inter <= __fmul_rn(0.6998f, denom)) return false;
    return __fdiv_rn(inter, denom) >= 0.7f;       // borderline: exact
}

// Fixed monotone binning for scores > 0.5 (clamped; monotone non-decreasing).
__device__ __forceinline__ unsigned score_bin(unsigned sb)
{
    unsigned d = (sb - 0x3F000000u) >> 15;
    return d > 255u ? 255u : d;
}

__global__ __launch_bounds__(NTHREADS, 1)
void nms_kernel(const float* __restrict__ proposals,
                const float* __restrict__ cls_scores,
                float* __restrict__ out)
{
    __shared__ unsigned long long skey[NBOX];   // vlist / sort arena (32 KB)
    __shared__ unsigned int hist[256];
    __shared__ unsigned int suf[257];
    __shared__ float4 kbox[KEPT_PAD];
    __shared__ float  karea[KEPT_PAD];
    __shared__ int    kidx[KEPT_PAD];
    __shared__ float4 cb[CHUNK];                // >1024 fallback staging only
    __shared__ float  car[CHUNK];
    __shared__ unsigned int chMaskLo[CHUNK];
    __shared__ unsigned int chMaskHi[CHUNK];
    __shared__ unsigned int supMask[2];
    __shared__ unsigned int sVCtr, sSelCtr;
    __shared__ int sCnt, sBinHi, sBinLo, sSelN;

    // Rank-path regions carved inside skey (selN <= RANKMAX only):
    unsigned long long* keysUn    = skey;                      // [0..383]
    unsigned long long* sortedKey = skey + 384;                // [384..767]
    int*    partial = (int*)(skey + 768);                      // 768 ints
    float4* bbufS   = (float4*)(skey + 1152);                  // 384 float4
    float*  abufS   = (float*)(skey + 1920);                   // 384 float
    float4* bbufUn  = (float4*)(skey + 2112);                  // 384 float4
    float*  aUn     = (float*)(skey + 2880);                   // 384 float
    // Legacy bitonic path regions (384 < selN <= 1024):
    float4* bbuf = (float4*)(skey + 1024);
    float*  abuf = (float*)(skey + 3072);

    const int b    = blockIdx.x;
    const int tid  = threadIdx.x;
    const int lane = tid & 31;
    const float* cls  = cls_scores + (size_t)b * NBOX * 2;
    const float* prop = proposals  + (size_t)b * NBOX * 4;

    if (tid == 0) { sVCtr = 0u; sCnt = 0; sBinHi = 255; }
    if (tid < 256) hist[tid] = 0u;
    // Prefetch this image's proposal slab (64 KB) into L2 for later gathers.
    if (tid < 512)
        asm volatile("prefetch.global.L2 [%0];" :: "l"((const char*)prop + tid * 128));
    __syncthreads();

    // ---- phase 0 (fused): validity + histogram + compacted vlist in smem ----
    #pragma unroll
    for (int t = 0; t < NBOX / NTHREADS; ++t) {
        int i = tid + t * NTHREADS;
        float s = __ldg(&cls[i * 2 + 1]);
        bool valid = s > 0.5f;                   // exact strict compare
        unsigned sb = __float_as_uint(s);
        if (valid) atomicAdd(&hist[score_bin(sb)], 1u);
        unsigned long long key =
            ((unsigned long long)sb << 32) | (unsigned)(NBOX - 1 - i);
        unsigned m = __ballot_sync(FULLM, valid);
        if (m) {
            int leader = __ffs(m) - 1;
            unsigned basep = 0;
            if (lane == leader) basep = atomicAdd(&sVCtr, (unsigned)__popc(m));
            basep = __shfl_sync(FULLM, basep, leader);
            if (valid) skey[basep + __popc(m & ((1u << lane) - 1u))] = key;
        }
    }
    __syncthreads();
    const int V = (int)sVCtr;

    if (tid < 256) {                             // suffix counts suf[t] = sum hist[t..255]
        unsigned sum = 0;
        for (int bb = tid; bb < 256; bb++) sum += hist[bb];
        suf[tid] = sum;
    }
    if (tid == 0) suf[256] = 0u;

    // ---- band loop: highest bins first; exact global descending order ----
    for (int iter = 0; iter < 260; ++iter) {
        __syncthreads();
        int cnt = sCnt, binHi = sBinHi;
        if (V == 0 || cnt >= MAXP || binHi < 0) break;

        if (tid == 0) {
            unsigned tail = suf[binHi + 1];
            int lo = 0;
            if (suf[0] - tail >= TARGET) {       // largest lo with band count >= TARGET
                int L = 0, R = binHi;
                while (L < R) {
                    int m = (L + R + 1) >> 1;
                    if (suf[m] - tail >= TARGET) L = m; else R = m - 1;
                }
                lo = L;
            }
            sBinLo = lo;
            sSelN  = (int)(suf[lo] - tail);
            sSelCtr = 0u;
        }
        __syncthreads();
        const int binLo = sBinLo, selN = sSelN;
        const bool rankPath = (selN > 0 && selN <= RANKMAX);

        if (selN > 0) {
            // ---- band extraction (rank path also gathers boxes) ----
            if (iter == 0) {
                unsigned long long r[4];
                #pragma unroll
                for (int t = 0; t < 4; ++t) {
                    int i = tid + t * NTHREADS;
                    r[t] = (i < V) ? skey[i] : 0ull;
                }
                __syncthreads();
                #pragma unroll
                for (int t = 0; t < 4; ++t) {
                    int i = tid + t * NTHREADS;
                    bool inband = false;
                    if (i < V) {
                        int bin = (int)score_bin((unsigned)(r[t] >> 32));
                        inband = (bin >= binLo && bin <= binHi);
                    }
                    unsigned m = __ballot_sync(FULLM, inband);
                    if (m) {
                        int leader = __ffs(m) - 1;
                        unsigned basep = 0;
                        if (lane == leader) basep = atomicAdd(&sSelCtr, (unsigned)__popc(m));
                        basep = __shfl_sync(FULLM, basep, leader);
                        if (inband) {
                            unsigned p = basep + __popc(m & ((1u << lane) - 1u));
                            keysUn[p] = r[t];
                            if (rankPath) {
                                int oi = NBOX - 1 - (int)(unsigned)(r[t] & 0xFFFFFFFFull);
                                float4 bb = *(const float4*)(prop + (size_t)oi * 4);
                                bbufUn[p] = bb;
                                aUn[p]    = __fmul_rn(bb.z - bb.x, bb.w - bb.y);
                            }
                        }
                    }
                }
            } else {
                #pragma unroll
                for (int t = 0; t < NBOX / NTHREADS; ++t) {
                    int i = tid + t * NTHREADS;
                    float s = __ldg(&cls[i * 2 + 1]);
                    bool inband = false;
                    unsigned sb = __float_as_uint(s);
                    if (s > 0.5f) {
                        int bin = (int)score_bin(sb);
                        inband = (bin >= binLo && bin <= binHi);
                    }
                    unsigned long long key =
                        ((unsigned long long)sb << 32) | (unsigned)(NBOX - 1 - i);
                    unsigned m = __ballot_sync(FULLM, inband);
                    if (m) {
                        int leader = __ffs(m) - 1;
                        unsigned basep = 0;
                        if (lane == leader) basep = atomicAdd(&sSelCtr, (unsigned)__popc(m));
                        basep = __shfl_sync(FULLM, basep, leader);
                        if (inband) {
                            unsigned p = basep + __popc(m & ((1u << lane) - 1u));
                            keysUn[p] = key;
                            if (rankPath) {
                                int oi = NBOX - 1 - (int)(unsigned)(key & 0xFFFFFFFFull);
                                float4 bb = *(const float4*)(prop + (size_t)oi * 4);
                                bbufUn[p] = bb;
                                aUn[p]    = __fmul_rn(bb.z - bb.x, bb.w - bb.y);
                            }
                        }
                    }
                }
            }
            __syncthreads();

            if (rankPath) {
                // ---- rank-scatter sort: rank(i) = #{j: key_j > key_i} ----
                const int half = (selN + 1) >> 1;
                if (tid < 2 * selN) {
                    int owner = (tid < selN) ? tid : tid - selN;
                    int j0    = (tid < selN) ? 0 : half;
                    int j1    = (tid < selN) ? half : selN;
                    unsigned long long ki = keysUn[owner];
                    int r = 0;
                    for (int j = j0; j < j1; ++j)
                        r += (keysUn[j] > ki) ? 1 : 0;
                    partial[tid] = r;
                }
                __syncthreads();
                if (tid < selN) {
                    int rk = partial[tid] + partial[tid + selN];
                    sortedKey[rk] = keysUn[tid];
                    bbufS[rk]     = bbufUn[tid];
                    abufS[rk]     = aUn[tid];
                }
                __syncthreads();
            } else if (selN <= 1024) {
                // ---- hybrid register/shfl bitonic (fallback), descending ----
                int S = 32; while (S < selN) S <<= 1;
                for (int i = tid; i < S; i += NTHREADS)
                    if (i >= selN) skey[i] = 0ull;
                __syncthreads();

                unsigned long long x = 0ull;
                if (tid < S) {
                    x = skey[tid];
                    #pragma unroll
                    for (int k = 2; k <= 32; k <<= 1) {
                        #pragma unroll
                        for (int j = k >> 1; j > 0; j >>= 1) {
                            unsigned long long y = __shfl_xor_sync(FULLM, x, j);
                            bool up      = ((tid & k) != 0);
                            bool lower   = ((tid & j) == 0);
                            bool wantMin = (lower == up);
                            if (wantMin ? (y < x) : (y > x)) x = y;
                        }
                    }
                    skey[tid] = x;
                }
                __syncthreads();

                for (int k = 64; k <= S; k <<= 1) {
                    for (int j = k >> 1; j >= 32; j >>= 1) {
                        if (tid < S) {
                            int i = tid, ixj = i ^ j;
                            if (ixj > i) {
                                unsigned long long ka = skey[i], kb = skey[ixj];
                                bool beforeBA = (kb > ka);
                                bool dir = ((i & k) == 0);
                                if (beforeBA == dir) { skey[i] = kb; skey[ixj] = ka; }
                            }
                        }
                        __syncthreads();
                    }
                    if (tid < S) {
                        x = skey[tid];
                        #pragma unroll
                        for (int j = 16; j > 0; j >>= 1) {
                            unsigned long long y = __shfl_xor_sync(FULLM, x, j);
                            bool up      = ((tid & k) != 0);
                            bool lower   = ((tid & j) == 0);
                            bool wantMin = (lower == up);
                            if (wantMin ? (y < x) : (y > x)) x = y;
                        }
                        skey[tid] = x;
                    }
                    __syncthreads();
                }
                // gather band boxes into smem
                for (int i = tid; i < selN; i += NTHREADS) {
                    int oi = NBOX - 1 - (int)(unsigned)(skey[i] & 0xFFFFFFFFull);
                    float4 bb = *(const float4*)(prop + (size_t)oi * 4);
                    bbuf[i] = bb;
                    abuf[i] = __fmul_rn(bb.z - bb.x, bb.w - bb.y);
                }
            } else {
                // ---- full smem bitonic (oversized tie band) ----
                int S = 1; while (S < selN) S <<= 1;
                for (int i = tid; i < S; i += NTHREADS)
                    if (i >= selN) skey[i] = 0ull;
                __syncthreads();
                for (int k = 2; k <= S; k <<= 1) {
                    for (int j = k >> 1; j > 0; j >>= 1) {
                        for (int i = tid; i < S; i += NTHREADS) {
                            int ixj = i ^ j;
                            if (ixj > i) {
                                unsigned long long ka = skey[i], kb = skey[ixj];
                                bool beforeBA = (kb > ka);
                                bool dir = ((i & k) == 0);
                                if (beforeBA == dir) { skey[i] = kb; skey[ixj] = ka; }
                            }
                        }
                        __syncthreads();
                    }
                }
            }
            if (tid < CHUNK) { chMaskLo[tid] = 0u; chMaskHi[tid] = 0u; }
            if (tid < 2) supMask[tid] = 0u;
            __syncthreads();

            const unsigned long long* skref = rankPath ? sortedKey : skey;

            // ---- chunk-parallel greedy NMS over this band ----
            for (int base = 0; base < selN; base += CHUNK) {
                int c0 = sCnt;                       // barrier-protected uniform read
                if (c0 >= MAXP) break;
                const int chunkN = (selN - base < CHUNK) ? (selN - base) : CHUNK;

                const float4* cB;
                const float*  cA;
                if (rankPath)            { cB = bbufS + base; cA = abufS + base; }
                else if (selN <= 1024)   { cB = bbuf + base;  cA = abuf + base; }
                else {
                    if (tid < chunkN) {              // fallback staging from global
                        int oi = NBOX - 1 - (int)(unsigned)(skey[base + tid] & 0xFFFFFFFFull);
                        float4 bb = *(const float4*)(prop + (size_t)oi * 4);
                        cb[tid]  = bb;
                        car[tid] = __fmul_rn(bb.z - bb.x, bb.w - bb.y);
                    }
                    __syncthreads();
                    cB = cb;
                    cA = car;
                }

                // fused IoU dispatch: candidate c fixed per thread for both loops
                {
                    const int c  = tid & (CHUNK - 1);
                    const int t0 = tid >> 6;         // 0..15
                    if (c < chunkN) {
                        const float4 cc = cB[c];
                        const float  ca = cA[c];
                        // vs already-kept, strided, unrolled x2
                        bool sup = false;
                        int t = t0;
                        for (; t + 16 < c0; t += 32) {
                            bool s1 = iou_ge(cc, ca, kbox[t],      karea[t]);
                            bool s2 = iou_ge(cc, ca, kbox[t + 16], karea[t + 16]);
                            if (s1 | s2) { sup = true; break; }
                        }
                        if (!sup)
                            for (; t < c0; t += 16)
                                if (iou_ge(cc, ca, kbox[t], karea[t])) { sup = true; break; }
                        if (sup) atomicOr(&supMask[c >> 5], 1u << (c & 31));
                        // within-chunk: earlier candidate i vs this c (IoU symmetric)
                        #pragma unroll
                        for (int h = 0; h < 4; ++h) {
                            int i = t0 + h * 16;
                            if (i < c && iou_ge(cc, ca, cB[i], cA[i])) {
                                if (c < 32) atomicOr(&chMaskLo[i], 1u << c);
                                else        atomicOr(&chMaskHi[i], 1u << (c - 32));
                            }
                        }
                    }
                }
                __syncthreads();

                // ---- sparse resolve (warp 0): walk only nonzero-mask candidates ----
                if (tid < 32) {
                    unsigned long long m64a =
                        ((unsigned long long)chMaskHi[tid] << 32) | chMaskLo[tid];
                    unsigned long long m64b =
                        ((unsigned long long)chMaskHi[tid + 32] << 32) | chMaskLo[tid + 32];
                    unsigned long long sup =
                        ((unsigned long long)supMask[1] << 32) | supMask[0];
                    unsigned actLo = __ballot_sync(FULLM, m64a != 0ull);
                    unsigned actHi = __ballot_sync(FULLM, m64b != 0ull);
                    unsigned long long act =
                        ((unsigned long long)actHi << 32) | actLo;
                    while (act) {                    // typically 0-3 iterations
                        int c = __ffsll(act) - 1;
                        act &= act - 1ull;
                        if (!((sup >> c) & 1ull)) {
                            unsigned long long m = (c < 32)
                                ? __shfl_sync(FULLM, m64a, c)
                                : __shfl_sync(FULLM, m64b, c - 32);
                            sup |= m;
                        }
                    }
                    unsigned long long kept = ~sup;
                    if (chunkN < 64) kept &= (1ull << chunkN) - 1ull;
                    int limit = MAXP - c0;
                    int excess = __popcll(kept) - limit;
                    while (excess > 0) {             // truncate to lowest `limit` bits
                        kept &= ~(1ull << (63 - __clzll(kept)));
                        excess--;
                    }
                    int c2 = c0 + __popcll(kept);
                    #pragma unroll
                    for (int h = 0; h < 2; ++h) {
                        int c = tid + h * 32;
                        if (c < chunkN && ((kept >> c) & 1ull)) {
                            int slot = c0 + __popcll(kept & ((1ull << c) - 1ull));
                            kbox[slot]  = cB[c];
                            karea[slot] = cA[c];
                            kidx[slot]  = NBOX - 1 -
                                (int)(unsigned)(skref[base + c] & 0xFFFFFFFFull);
                        }
                    }
                    chMaskLo[tid] = 0u; chMaskHi[tid] = 0u;
                    chMaskLo[tid + 32] = 0u; chMaskHi[tid + 32] = 0u;
                    if (tid < 2) supMask[tid] = 0u;
                    if (tid == 0) sCnt = c2;
                }
                __syncthreads();
            }
        }
        if (tid == 0) sBinHi = binLo - 1;
    }

    __syncthreads();
    // ---- epilogue: pad with last kept; nk==0 (<=> V==0) -> order[n-1] = 4095 ----
    const int nk = sCnt;
    float* outBoxes  = out;                              // [16,300,4]
    float* outScores = out + (size_t)BATCH * MAXP * 4;   // [16,300]
    for (int k = tid; k < MAXP; k += NTHREADS) {
        float4 bb; int sel;
        if (nk == 0) {
            sel = NBOX - 1;
            bb = *(const float4*)(prop + (size_t)sel * 4);
        } else {
            int kk = k < nk ? k : nk - 1;
            bb = kbox[kk];
            sel = kidx[kk];
        }
        *(float4*)(outBoxes + ((size_t)b * MAXP + k) * 4) = bb;
        outScores[(size_t)b * MAXP + k] = __ldg(&cls[sel * 2 + 1]);
    }
}

extern "C" void kernel_launch(void* const* d_in, const int* in_sizes, int n_in,
                              void* d_out, int out_size)
{
    const float* proposals = (const float*)d_in[0];   // [16,4096,4] f32
    const float* cls       = (const float*)d_in[1];   // [16,4096,2] f32
    float* out             = (float*)d_out;           // boxes then scores

    nms_kernel<<<BATCH, NTHREADS>>>(proposals, cls, out);
}

// round 17
// speedup vs baseline: 25.2218x; 1.1667x over previous
#include <cuda_runtime.h>

#define NBOX 4096
#define BATCH 16
#define MAXP 300
#define KEPT_PAD 304
#define NTHREADS 1024
#define CHUNK 64
#define TARGET 320
#define RANKMAX 384
#define FULLM 0xffffffffu

// IoU decision, bit-exact vs the reference's __fdiv_rn(inter,denom) >= 0.7f.
// Conservative multiply gates; only ratios in (0.6998, 0.7002) take the div.
__device__ __forceinline__ bool iou_ge(float4 a, float aa, float4 b, float ba)
{
    float ix1 = fmaxf(a.x, b.x);
    float iy1 = fmaxf(a.y, b.y);
    float ix2 = fminf(a.z, b.z);
    float iy2 = fminf(a.w, b.w);
    float w = fmaxf(ix2 - ix1, 0.0f);
    float h = fmaxf(iy2 - iy1, 0.0f);
    float inter = __fmul_rn(w, h);
    float denom = (aa + ba) - inter;
    if (inter >= __fmul_rn(0.7002f, denom)) return true;
    if (inter <= __fmul_rn(0.6998f, denom)) return false;
    return __fdiv_rn(inter, denom) >= 0.7f;       // borderline: exact
}

// Fixed monotone binning for scores > 0.5 (clamped; monotone non-decreasing).
__device__ __forceinline__ unsigned score_bin(unsigned sb)
{
    unsigned d = (sb - 0x3F000000u) >> 15;
    return d > 255u ? 255u : d;
}

__global__ __launch_bounds__(NTHREADS, 1)
void nms_kernel(const float* __restrict__ proposals,
                const float* __restrict__ cls_scores,
                float* __restrict__ out)
{
    __shared__ unsigned long long skey[NBOX];   // vlist / sort arena (32 KB)
    __shared__ unsigned int hist[256];
    __shared__ unsigned int suf[257];
    __shared__ unsigned int cntA[256];
    __shared__ unsigned int exc[256];
    __shared__ unsigned int warpTot[8];
    __shared__ float4 kbox[KEPT_PAD];
    __shared__ float  karea[KEPT_PAD];
    __shared__ int    kidx[KEPT_PAD];
    __shared__ float4 cb[CHUNK];                // >1024 fallback staging only
    __shared__ float  car[CHUNK];
    __shared__ unsigned int chMaskLo[CHUNK];
    __shared__ unsigned int chMaskHi[CHUNK];
    __shared__ unsigned int supMask[2];
    __shared__ unsigned int sVCtr, sSelCtr;
    __shared__ int sCnt, sBinHi, sBinLo, sSelN;

    // Rank-path arena inside skey (selN <= RANKMAX only), u64 offsets:
    unsigned long long* keysUn    = skey;                 // [0..384)
    float4* bbufUn  = (float4*)(skey + 384);              // [384..1152)
    float*  aUn     = (float*)(skey + 1152);              // [1152..1344)
    unsigned long long* sortedKey = skey + 1344;          // [1344..1728)
    float4* bbufS   = (float4*)(skey + 1728);             // [1728..2496)
    float*  abufS   = (float*)(skey + 2496);              // [2496..2688)
    unsigned long long* gKey      = skey + 2688;          // [2688..3072)
    // Bitonic path (384 < selN <= 1024): keys [0..1024) +
    float4* bbuf = (float4*)(skey + 1024);
    float*  abuf = (float*)(skey + 3072);

    const int b    = blockIdx.x;
    const int tid  = threadIdx.x;
    const int lane = tid & 31;
    const float* cls  = cls_scores + (size_t)b * NBOX * 2;
    const float* prop = proposals  + (size_t)b * NBOX * 4;

    if (tid == 0) { sVCtr = 0u; sCnt = 0; sBinHi = 255; }
    if (tid < 256) hist[tid] = 0u;
    // Prefetch this image's proposal slab (64 KB) into L2 for later gathers.
    if (tid < 512)
        asm volatile("prefetch.global.L2 [%0];" :: "l"((const char*)prop + tid * 128));
    __syncthreads();

    // ---- phase 0 (fused): batched loads + validity + histogram + vlist ----
    float sv[4];
    #pragma unroll
    for (int t = 0; t < 4; ++t)
        sv[t] = __ldg(&cls[(tid + t * NTHREADS) * 2 + 1]);   // MLP=4
    #pragma unroll
    for (int t = 0; t < 4; ++t) {
        int i = tid + t * NTHREADS;
        float s = sv[t];
        bool valid = s > 0.5f;                   // exact strict compare
        unsigned sb = __float_as_uint(s);
        if (valid) atomicAdd(&hist[score_bin(sb)], 1u);
        unsigned long long key =
            ((unsigned long long)sb << 32) | (unsigned)(NBOX - 1 - i);
        unsigned m = __ballot_sync(FULLM, valid);
        if (m) {
            int leader = __ffs(m) - 1;
            unsigned basep = 0;
            if (lane == leader) basep = atomicAdd(&sVCtr, (unsigned)__popc(m));
            basep = __shfl_sync(FULLM, basep, leader);
            if (valid) skey[basep + __popc(m & ((1u << lane) - 1u))] = key;
        }
    }
    __syncthreads();
    const int V = (int)sVCtr;

    // ---- parallel suffix counts: suf[t] = sum hist[t..255] ----
    unsigned sufTot = 0;
    if (tid < 256) {
        sufTot = hist[tid];
        #pragma unroll
        for (int off = 1; off < 32; off <<= 1) {
            unsigned y = __shfl_down_sync(FULLM, sufTot, off);
            if (lane + off < 32) sufTot += y;
        }
        if (lane == 0) warpTot[tid >> 5] = sufTot;   // warp totals
    }
    __syncthreads();
    if (tid < 256) {
        unsigned add = 0;
        int w = tid >> 5;
        for (int w2 = w + 1; w2 < 8; ++w2) add += warpTot[w2];
        suf[tid] = sufTot + add;
    }
    if (tid == 0) suf[256] = 0u;

    // ---- band loop: highest bins first; exact global descending order ----
    for (int iter = 0; iter < 260; ++iter) {
        __syncthreads();
        int cnt = sCnt, binHi = sBinHi;
        if (V == 0 || cnt >= MAXP || binHi < 0) break;

        if (tid == 0) {
            unsigned tail = suf[binHi + 1];
            int lo = 0;
            if (suf[0] - tail >= TARGET) {       // largest lo with band count >= TARGET
                int L = 0, R = binHi;
                while (L < R) {
                    int m = (L + R + 1) >> 1;
                    if (suf[m] - tail >= TARGET) L = m; else R = m - 1;
                }
                lo = L;
            }
            sBinLo = lo;
            sSelN  = (int)(suf[lo] - tail);
            sSelCtr = 0u;
        }
        __syncthreads();
        const int binLo = sBinLo, selN = sSelN;
        const bool rankPath = (selN > 0 && selN <= RANKMAX);

        if (selN > 0) {
            // ---- band extraction (rank path also gathers boxes) ----
            if (iter == 0) {
                unsigned long long r[4];
                #pragma unroll
                for (int t = 0; t < 4; ++t) {
                    int i = tid + t * NTHREADS;
                    r[t] = (i < V) ? skey[i] : 0ull;
                }
                __syncthreads();
                #pragma unroll
                for (int t = 0; t < 4; ++t) {
                    int i = tid + t * NTHREADS;
                    bool inband = false;
                    if (i < V) {
                        int bin = (int)score_bin((unsigned)(r[t] >> 32));
                        inband = (bin >= binLo && bin <= binHi);
                    }
                    unsigned m = __ballot_sync(FULLM, inband);
                    if (m) {
                        int leader = __ffs(m) - 1;
                        unsigned basep = 0;
                        if (lane == leader) basep = atomicAdd(&sSelCtr, (unsigned)__popc(m));
                        basep = __shfl_sync(FULLM, basep, leader);
                        if (inband) {
                            unsigned p = basep + __popc(m & ((1u << lane) - 1u));
                            keysUn[p] = r[t];
                            if (rankPath) {
                                int oi = NBOX - 1 - (int)(unsigned)(r[t] & 0xFFFFFFFFull);
                                float4 bb = *(const float4*)(prop + (size_t)oi * 4);
                                bbufUn[p] = bb;
                                aUn[p]    = __fmul_rn(bb.z - bb.x, bb.w - bb.y);
                            }
                        }
                    }
                }
            } else {
                #pragma unroll
                for (int t = 0; t < 4; ++t) {
                    int i = tid + t * NTHREADS;
                    float s = __ldg(&cls[i * 2 + 1]);
                    bool inband = false;
                    unsigned sb = __float_as_uint(s);
                    if (s > 0.5f) {
                        int bin = (int)score_bin(sb);
                        inband = (bin >= binLo && bin <= binHi);
                    }
                    unsigned long long key =
                        ((unsigned long long)sb << 32) | (unsigned)(NBOX - 1 - i);
                    unsigned m = __ballot_sync(FULLM, inband);
                    if (m) {
                        int leader = __ffs(m) - 1;
                        unsigned basep = 0;
                        if (lane == leader) basep = atomicAdd(&sSelCtr, (unsigned)__popc(m));
                        basep = __shfl_sync(FULLM, basep, leader);
                        if (inband) {
                            unsigned p = basep + __popc(m & ((1u << lane) - 1u));
                            keysUn[p] = key;
                            if (rankPath) {
                                int oi = NBOX - 1 - (int)(unsigned)(key & 0xFFFFFFFFull);
                                float4 bb = *(const float4*)(prop + (size_t)oi * 4);
                                bbufUn[p] = bb;
                                aUn[p]    = __fmul_rn(bb.z - bb.x, bb.w - bb.y);
                            }
                        }
                    }
                }
            }
            __syncthreads();

            if (rankPath) {
                // ---- counting-sort ranking (exact, unique keys) ----
                // Sub-bin: monotone slice of the band's score-bit span.
                unsigned sbLo = 0x3F000000u + ((unsigned)binLo << 15);
                unsigned sbHi = (binHi >= 255) ? 0x3F800000u
                                               : 0x3F000000u + ((unsigned)(binHi + 1) << 15);
                unsigned span = sbHi - sbLo;
                int shift = 32 - __clz(span) - 8;
                if (shift < 0) shift = 0;

                if (tid < 256) cntA[tid] = 0u;
                __syncthreads();

                unsigned long long myKey = 0ull;
                int myBin = 0;
                if (tid < selN) {
                    myKey = keysUn[tid];
                    unsigned d = ((unsigned)(myKey >> 32) - sbLo) >> shift;
                    myBin = d > 255u ? 255 : (int)d;
                    atomicAdd(&cntA[myBin], 1u);
                }
                __syncthreads();

                // exclusive ascending prefix of cntA -> exc; reset cntA as cursor
                unsigned rawv = 0, incl = 0;
                if (tid < 256) {
                    rawv = cntA[tid];
                    incl = rawv;
                    #pragma unroll
                    for (int off = 1; off < 32; off <<= 1) {
                        unsigned y = __shfl_up_sync(FULLM, incl, off);
                        if (lane >= off) incl += y;
                    }
                    if (lane == 31) warpTot[tid >> 5] = incl;
                }
                __syncthreads();
                if (tid < 256) {
                    unsigned add = 0;
                    int w = tid >> 5;
                    for (int w2 = 0; w2 < w; ++w2) add += warpTot[w2];
                    exc[tid]  = incl + add - rawv;
                    cntA[tid] = 0u;
                }
                __syncthreads();

                if (tid < selN) {                        // grouped placement
                    unsigned pos = atomicAdd(&cntA[myBin], 1u);
                    gKey[exc[myBin] + pos] = myKey;
                }
                __syncthreads();

                if (tid < selN) {                        // rank + scatter
                    unsigned basep = exc[myBin];
                    unsigned nb = cntA[myBin];           // raw count restored
                    unsigned gt = 0;
                    for (unsigned g = basep; g < basep + nb; ++g)
                        gt += (gKey[g] > myKey) ? 1u : 0u;
                    int rk = (int)((unsigned)selN - (basep + nb)) + (int)gt;
                    sortedKey[rk] = myKey;
                    bbufS[rk] = bbufUn[tid];
                    abufS[rk] = aUn[tid];
                }
                __syncthreads();
            } else if (selN <= 1024) {
                // ---- hybrid register/shfl bitonic (fallback), descending ----
                int S = 32; while (S < selN) S <<= 1;
                for (int i = tid; i < S; i += NTHREADS)
                    if (i >= selN) skey[i] = 0ull;
                __syncthreads();

                unsigned long long x = 0ull;
                if (tid < S) {
                    x = skey[tid];
                    #pragma unroll
                    for (int k = 2; k <= 32; k <<= 1) {
                        #pragma unroll
                        for (int j = k >> 1; j > 0; j >>= 1) {
                            unsigned long long y = __shfl_xor_sync(FULLM, x, j);
                            bool up      = ((tid & k) != 0);
                            bool lower   = ((tid & j) == 0);
                            bool wantMin = (lower == up);
                            if (wantMin ? (y < x) : (y > x)) x = y;
                        }
                    }
                    skey[tid] = x;
                }
                __syncthreads();

                for (int k = 64; k <= S; k <<= 1) {
                    for (int j = k >> 1; j >= 32; j >>= 1) {
                        if (tid < S) {
                            int i = tid, ixj = i ^ j;
                            if (ixj > i) {
                                unsigned long long ka = skey[i], kb = skey[ixj];
                                bool beforeBA = (kb > ka);
                                bool dir = ((i & k) == 0);
                                if (beforeBA == dir) { skey[i] = kb; skey[ixj] = ka; }
                            }
                        }
                        __syncthreads();
                    }
                    if (tid < S) {
                        x = skey[tid];
                        #pragma unroll
                        for (int j = 16; j > 0; j >>= 1) {
                            unsigned long long y = __shfl_xor_sync(FULLM, x, j);
                            bool up      = ((tid & k) != 0);
                            bool lower   = ((tid & j) == 0);
                            bool wantMin = (lower == up);
                            if (wantMin ? (y < x) : (y > x)) x = y;
                        }
                        skey[tid] = x;
                    }
                    __syncthreads();
                }
                // gather band boxes into smem
                for (int i = tid; i < selN; i += NTHREADS) {
                    int oi = NBOX - 1 - (int)(unsigned)(skey[i] & 0xFFFFFFFFull);
                    float4 bb = *(const float4*)(prop + (size_t)oi * 4);
                    bbuf[i] = bb;
                    abuf[i] = __fmul_rn(bb.z - bb.x, bb.w - bb.y);
                }
            } else {
                // ---- full smem bitonic (oversized tie band) ----
                int S = 1; while (S < selN) S <<= 1;
                for (int i = tid; i < S; i += NTHREADS)
                    if (i >= selN) skey[i] = 0ull;
                __syncthreads();
                for (int k = 2; k <= S; k <<= 1) {
                    for (int j = k >> 1; j > 0; j >>= 1) {
                        for (int i = tid; i < S; i += NTHREADS) {
                            int ixj = i ^ j;
                            if (ixj > i) {
                                unsigned long long ka = skey[i], kb = skey[ixj];
                                bool beforeBA = (kb > ka);
                                bool dir = ((i & k) == 0);
                                if (beforeBA == dir) { skey[i] = kb; skey[ixj] = ka; }
                            }
                        }
                        __syncthreads();
                    }
                }
            }
            if (tid < CHUNK) { chMaskLo[tid] = 0u; chMaskHi[tid] = 0u; }
            if (tid < 2) supMask[tid] = 0u;
            __syncthreads();

            const unsigned long long* skref = rankPath ? sortedKey : skey;

            // ---- chunk-parallel greedy NMS over this band ----
            for (int base = 0; base < selN; base += CHUNK) {
                int c0 = sCnt;                       // barrier-protected uniform read
                if (c0 >= MAXP) break;
                const int chunkN = (selN - base < CHUNK) ? (selN - base) : CHUNK;

                const float4* cB;
                const float*  cA;
                if (rankPath)            { cB = bbufS + base; cA = abufS + base; }
                else if (selN <= 1024)   { cB = bbuf + base;  cA = abuf + base; }
                else {
                    if (tid < chunkN) {              // fallback staging from global
                        int oi = NBOX - 1 - (int)(unsigned)(skey[base + tid] & 0xFFFFFFFFull);
                        float4 bb = *(const float4*)(prop + (size_t)oi * 4);
                        cb[tid]  = bb;
                        car[tid] = __fmul_rn(bb.z - bb.x, bb.w - bb.y);
                    }
                    __syncthreads();
                    cB = cb;
                    cA = car;
                }

                // fused IoU dispatch: candidate c fixed per thread for both loops
                {
                    const int c  = tid & (CHUNK - 1);
                    const int t0 = tid >> 6;         // 0..15
                    if (c < chunkN) {
                        const float4 cc = cB[c];
                        const float  ca = cA[c];
                        // vs already-kept, strided, unrolled x2
                        bool sup = false;
                        int t = t0;
                        for (; t + 16 < c0; t += 32) {
                            bool s1 = iou_ge(cc, ca, kbox[t],      karea[t]);
                            bool s2 = iou_ge(cc, ca, kbox[t + 16], karea[t + 16]);
                            if (s1 | s2) { sup = true; break; }
                        }
                        if (!sup)
                            for (; t < c0; t += 16)
                                if (iou_ge(cc, ca, kbox[t], karea[t])) { sup = true; break; }
                        if (sup) atomicOr(&supMask[c >> 5], 1u << (c & 31));
                        // within-chunk: earlier candidate i vs this c (IoU symmetric)
                        #pragma unroll
                        for (int h = 0; h < 4; ++h) {
                            int i = t0 + h * 16;
                            if (i < c && iou_ge(cc, ca, cB[i], cA[i])) {
                                if (c < 32) atomicOr(&chMaskLo[i], 1u << c);
                                else        atomicOr(&chMaskHi[i], 1u << (c - 32));
                            }
                        }
                    }
                }
                __syncthreads();

                // ---- sparse resolve (warp 0): walk only nonzero-mask candidates ----
                if (tid < 32) {
                    unsigned long long m64a =
                        ((unsigned long long)chMaskHi[tid] << 32) | chMaskLo[tid];
                    unsigned long long m64b =
                        ((unsigned long long)chMaskHi[tid + 32] << 32) | chMaskLo[tid + 32];
                    unsigned long long sup =
                        ((unsigned long long)supMask[1] << 32) | supMask[0];
                    unsigned actLo = __ballot_sync(FULLM, m64a != 0ull);
                    unsigned actHi = __ballot_sync(FULLM, m64b != 0ull);
                    unsigned long long act =
                        ((unsigned long long)actHi << 32) | actLo;
                    while (act) {                    // typically 0-3 iterations
                        int c = __ffsll(act) - 1;
                        act &= act - 1ull;
                        if (!((sup >> c) & 1ull)) {
                            unsigned long long m = (c < 32)
                                ? __shfl_sync(FULLM, m64a, c)
                                : __shfl_sync(FULLM, m64b, c - 32);
                            sup |= m;
                        }
                    }
                    unsigned long long kept = ~sup;
                    if (chunkN < 64) kept &= (1ull << chunkN) - 1ull;
                    int limit = MAXP - c0;
                    int excess = __popcll(kept) - limit;
                    while (excess > 0) {             // truncate to lowest `limit` bits
                        kept &= ~(1ull << (63 - __clzll(kept)));
                        excess--;
                    }
                    int c2 = c0 + __popcll(kept);
                    #pragma unroll
                    for (int h = 0; h < 2; ++h) {
                        int c = tid + h * 32;
                        if (c < chunkN && ((kept >> c) & 1ull)) {
                            int slot = c0 + __popcll(kept & ((1ull << c) - 1ull));
                            kbox[slot]  = cB[c];
                            karea[slot] = cA[c];
                            kidx[slot]  = NBOX - 1 -
                                (int)(unsigned)(skref[base + c] & 0xFFFFFFFFull);
                        }
                    }
                    chMaskLo[tid] = 0u; chMaskHi[tid] = 0u;
                    chMaskLo[tid + 32] = 0u; chMaskHi[tid + 32] = 0u;
                    if (tid < 2) supMask[tid] = 0u;
                    if (tid == 0) sCnt = c2;
                }
                __syncthreads();
            }
        }
        if (tid == 0) sBinHi = binLo - 1;
    }

    __syncthreads();
    // ---- epilogue: pad with last kept; nk==0 (<=> V==0) -> order[n-1] = 4095 ----
    const int nk = sCnt;
    float* outBoxes  = out;                              // [16,300,4]
    float* outScores = out + (size_t)BATCH * MAXP * 4;   // [16,300]
    for (int k = tid; k < MAXP; k += NTHREADS) {
        float4 bb; int sel;
        if (nk == 0) {
            sel = NBOX - 1;
            bb = *(const float4*)(prop + (size_t)sel * 4);
        } else {
            int kk = k < nk ? k : nk - 1;
            bb = kbox[kk];
            sel = kidx[kk];
        }
        *(float4*)(outBoxes + ((size_t)b * MAXP + k) * 4) = bb;
        outScores[(size_t)b * MAXP + k] = __ldg(&cls[sel * 2 + 1]);
    }
}

extern "C" void kernel_launch(void* const* d_in, const int* in_sizes, int n_in,
                              void* d_out, int out_size)
{
    const float* proposals = (const float*)d_in[0];   // [16,4096,4] f32
    const float* cls       = (const float*)d_in[1];   // [16,4096,2] f32
    float* out             = (float*)d_out;           // boxes then scores

    nms_kernel<<<BATCH, NTHREADS>>>(proposals, cls, out);
}